// round 11
// baseline (speedup 1.0000x reference)
#include <cuda_runtime.h>
#include <cuda_fp16.h>
#include <math.h>
#include <stdint.h>

#define B 8
#define C 64
#define H 256
#define W 256
#define OCH 128
#define K2 9
#define HO 128
#define WO 128
#define CK 576

// ---------------- device scratch (allocation-free) ----------------
__device__ __align__(16) float g_xt[B * H * W * C];    // x NHWC fp32
__device__ __align__(16) uint4 g_wfM[9 * 4 * 8 * 32];  // main A frags [t][ks][f][lane]
__device__ __align__(16) uint4 g_wfOh[9 * 4 * 2 * 32]; // offset A frags hi
__device__ __align__(16) uint4 g_wfOl[9 * 4 * 2 * 32]; // offset A frags lo
__device__ __align__(16) float4 g_gw[B * HO * WO * 9]; // bilinear weights (mask folded)
__device__ __align__(16) uint2  g_gd[B * HO * WO * 9]; // base elem idx, (dx | dy<<16)

__device__ __forceinline__ uint32_t smem_u32(const void* p) {
    uint32_t a;
    asm("{ .reg .u64 t; cvta.to.shared.u64 t, %1; cvt.u32.u64 %0, t; }"
        : "=r"(a) : "l"(p));
    return a;
}
__device__ __forceinline__ uint32_t sw128(uint32_t off) {
    return off ^ ((off >> 3) & 0x70);
}
__device__ __forceinline__ uint32_t pack_h2(float a, float b) {
    __half2 t = __floats2half2_rn(a, b);
    return *(uint32_t*)&t;
}
#define LDMX4(r0, r1, r2, r3, addr)                                          \
    asm volatile("ldmatrix.sync.aligned.m8n8.x4.shared.b16 {%0,%1,%2,%3}, [%4];" \
                 : "=r"(r0), "=r"(r1), "=r"(r2), "=r"(r3) : "r"(addr))
#define LDMX2(r0, r1, addr)                                                  \
    asm volatile("ldmatrix.sync.aligned.m8n8.x2.shared.b16 {%0,%1}, [%2];"    \
                 : "=r"(r0), "=r"(r1) : "r"(addr))
#define HMMA(acc, a, b)                                                       \
    asm volatile(                                                             \
        "mma.sync.aligned.m16n8k16.row.col.f32.f16.f16.f32 "                  \
        "{%0,%1,%2,%3}, {%4,%5,%6,%7}, {%8,%9}, {%0,%1,%2,%3};"               \
        : "+f"(acc[0]), "+f"(acc[1]), "+f"(acc[2]), "+f"(acc[3])              \
        : "r"(a[0]), "r"(a[1]), "r"(a[2]), "r"(a[3]), "r"(b[0]), "r"(b[1]))

// ---------------------------------------------------------------------------
// Kernel 0: NCHW fp32 -> NHWC fp32
// ---------------------------------------------------------------------------
__global__ void transpose_kernel(const float* __restrict__ x) {
    __shared__ float tile[64][33];
    int b  = blockIdx.z;
    int s0 = blockIdx.x * 32;
    int tx = threadIdx.x, ty = threadIdx.y;
    const float* xb = x + (size_t)b * (C * H * W);
#pragma unroll
    for (int cy = ty; cy < 64; cy += 8)
        tile[cy][tx] = xb[(size_t)cy * (H * W) + s0 + tx];
    __syncthreads();
    size_t obase = (size_t)b * (H * W * C);
#pragma unroll
    for (int pp = 0; pp < 4; pp++) {
        int p = ty + pp * 8;
        float2 v = make_float2(tile[2 * tx][p], tile[2 * tx + 1][p]);
        *(float2*)(g_xt + obase + (size_t)(s0 + p) * C + 2 * tx) = v;
    }
}

// ---------------------------------------------------------------------------
// Kernel 0b: main weights -> A fragments
// ---------------------------------------------------------------------------
__global__ void wfragM_kernel(const float* __restrict__ wt) {
    int j = blockIdx.x * 256 + threadIdx.x;
    if (j >= 9 * 4 * 8 * 32) return;
    int lane = j & 31;
    int f    = (j >> 5) & 7;
    int ks   = (j >> 8) & 3;
    int t    = j >> 10;
    int r  = lane >> 2;
    int c2 = lane & 3;
    int oc0 = f * 16 + r;
    int ch0 = ks * 16 + c2 * 2;
#define WV(oc, ch) wt[(oc) * CK + (ch) * 9 + t]
    uint4 o;
    o.x = pack_h2(WV(oc0, ch0),         WV(oc0, ch0 + 1));
    o.y = pack_h2(WV(oc0 + 8, ch0),     WV(oc0 + 8, ch0 + 1));
    o.z = pack_h2(WV(oc0, ch0 + 8),     WV(oc0, ch0 + 9));
    o.w = pack_h2(WV(oc0 + 8, ch0 + 8), WV(oc0 + 8, ch0 + 9));
#undef WV
    g_wfM[j] = o;
}

// ---------------------------------------------------------------------------
// Kernel 0c: offset weights -> A fragments hi/lo (M=32, rows>=27 zero)
// ---------------------------------------------------------------------------
__global__ void wfragO_kernel(const float* __restrict__ ow) {
    int j = blockIdx.x * 256 + threadIdx.x;
    if (j >= 9 * 4 * 2 * 32) return;
    int lane = j & 31;
    int mi   = (j >> 5) & 1;
    int ks   = (j >> 6) & 3;
    int t    = j >> 8;
    int r  = lane >> 2;
    int c2 = lane & 3;
    int oc0 = mi * 16 + r;
    int ch0 = ks * 16 + c2 * 2;

    float v[2][2][2];
#pragma unroll
    for (int rh = 0; rh < 2; rh++)
#pragma unroll
        for (int chh = 0; chh < 2; chh++)
#pragma unroll
            for (int e = 0; e < 2; e++) {
                int oc = oc0 + rh * 8;
                int ch = ch0 + chh * 8 + e;
                v[rh][chh][e] = (oc < 27) ? ow[(oc * 64 + ch) * 9 + t] : 0.0f;
            }
    uint4 oh, ol;
#define SPLIT(dsth, dstl, a, b)                                              \
    {                                                                         \
        __half2 hh = __floats2half2_rn(a, b);                                 \
        float2 hf = __half22float2(hh);                                       \
        dsth = *(uint32_t*)&hh;                                               \
        __half2 lls = __floats2half2_rn((a) - hf.x, (b) - hf.y);              \
        dstl = *(uint32_t*)&lls;                                              \
    }
    SPLIT(oh.x, ol.x, v[0][0][0], v[0][0][1]);
    SPLIT(oh.y, ol.y, v[1][0][0], v[1][0][1]);
    SPLIT(oh.z, ol.z, v[0][1][0], v[0][1][1]);
    SPLIT(oh.w, ol.w, v[1][1][0], v[1][1][1]);
#undef SPLIT
    g_wfOh[j] = oh;
    g_wfOl[j] = ol;
}

// ---------------------------------------------------------------------------
// Kernel 1: offset conv via split-fp16 mma + fused bilinear-param precompute.
// 512 threads (16 warps), warp tile M32 x N8. Block = (b,h): M=32(27) x N=128.
// smem 32KB: Bh@0, Bl@16384.
// ---------------------------------------------------------------------------
__global__ void __launch_bounds__(512, 2)
offset_mma_kernel(const float* __restrict__ ob) {
    extern __shared__ char smraw[];
    char* smb = (char*)(((uintptr_t)smraw + 1023) & ~(uintptr_t)1023);
    char* Bh = smb;
    char* Bl = smb + 16384;

    int tid  = threadIdx.x;
    int warp = tid >> 5;
    int lane = tid & 31;

    int blk = blockIdx.x;   // b*128 + h
    int b   = blk >> 7;
    int h   = blk & 127;

    // ldmatrix.x2 B address: lanes 0-15 give the 2 tile rows
    int bRowB = warp * 8 + (lane & 7);
    int bKoffB = ((lane >> 3) & 1) * 16;

    float acc[2][4];
#pragma unroll
    for (int mi = 0; mi < 2; mi++)
#pragma unroll
        for (int e = 0; e < 4; e++) acc[mi][e] = 0.0f;

    size_t xbase = (size_t)b * (H * W * C);
    int cch = lane * 2;
    uint32_t bhB = smem_u32(Bh);
    uint32_t blB = smem_u32(Bl);

    for (int t = 0; t < 9; t++) {
        // ---- gather tap t: 8 positions per warp ----
        {
            int ky = t / 3;
            int kx = t - ky * 3;
            int iy = 2 * h - 1 + ky;
            bool yok = (iy >= 0) && (iy < H);
            const float* rowb = g_xt + xbase + (size_t)iy * (W * C) + cch;
#pragma unroll
            for (int i = 0; i < 8; i++) {
                int p  = warp * 8 + i;
                int ix = 2 * p - 1 + kx;
                float2 v = make_float2(0.0f, 0.0f);
                if (yok && ix >= 0 && ix < W)
                    v = *(const float2*)(rowb + (size_t)ix * C);
                __half2 hh = __floats2half2_rn(v.x, v.y);
                float2 hf = __half22float2(hh);
                __half2 ll = __floats2half2_rn(v.x - hf.x, v.y - hf.y);
                uint32_t so = sw128((uint32_t)(p * 128 + lane * 4));
                *(uint32_t*)(Bh + so) = *(uint32_t*)&hh;
                *(uint32_t*)(Bl + so) = *(uint32_t*)&ll;
            }
        }
        __syncthreads();

#pragma unroll
        for (int ks = 0; ks < 4; ks++) {
            uint32_t ah[2][4], al[2][4], bh[2], bl[2];
#pragma unroll
            for (int mi = 0; mi < 2; mi++) {
                uint4 fh = g_wfOh[((t * 4 + ks) * 2 + mi) * 32 + lane];
                uint4 fl = g_wfOl[((t * 4 + ks) * 2 + mi) * 32 + lane];
                ah[mi][0] = fh.x; ah[mi][1] = fh.y; ah[mi][2] = fh.z; ah[mi][3] = fh.w;
                al[mi][0] = fl.x; al[mi][1] = fl.y; al[mi][2] = fl.z; al[mi][3] = fl.w;
            }
            {
                uint32_t boff = sw128((uint32_t)(bRowB * 128 + ks * 32 + bKoffB));
                LDMX2(bh[0], bh[1], bhB + boff);
                LDMX2(bl[0], bl[1], blB + boff);
            }
#pragma unroll
            for (int mi = 0; mi < 2; mi++) {
                HMMA(acc[mi], ah[mi], bh);
                HMMA(acc[mi], ah[mi], bl);
                HMMA(acc[mi], al[mi], bh);
            }
        }
        __syncthreads();
    }

    // ---- epilogue: offsets -> smem (reuse Bh region, 16KB) ----
    float* smOff = (float*)Bh;  // [128][32]
    {
        int ocb  = lane >> 2;
        int posb = warp * 8 + (lane & 3) * 2;
#pragma unroll
        for (int mi = 0; mi < 2; mi++) {
#pragma unroll
            for (int eh = 0; eh < 2; eh++) {
                int oc = mi * 16 + eh * 8 + ocb;
                if (oc >= 27) continue;
                float bv = ob[oc];
                bool sig = (oc >= 18);
#pragma unroll
                for (int e0 = 0; e0 < 2; e0++) {
                    float v = acc[mi][eh * 2 + e0] + bv;
                    if (sig) v = 1.0f / (1.0f + __expf(-v));
                    int pos = posb + e0;
                    smOff[pos * 32 + oc] = v;
                }
            }
        }
    }
    __syncthreads();

    // ---- param phase: 1152 (p,t) items ----
    float hyf = (float)(2 * h - 1);
    for (int j = tid; j < 128 * 9; j += 512) {
        int p = j / 9;
        int t = j - p * 9;
        float offx = smOff[p * 32 + t];
        float offy = smOff[p * 32 + 9 + t];
        float m    = smOff[p * 32 + 18 + t];

        float py = offy + (float)(t / 3) + hyf;
        float px = offx + (float)(t - (t / 3) * 3) + (float)(2 * p - 1);

        float y0f = floorf(py), x0f = floorf(px);
        float y1f = y0f + 1.0f, x1f = x0f + 1.0f;
        float wy1 = py - y0f, wy0 = 1.0f - wy1;
        float wx1 = px - x0f, wx0 = 1.0f - wx1;

        bool vy0 = (y0f >= 0.0f) && (y0f <= (float)(H - 1));
        bool vy1 = (y1f >= 0.0f) && (y1f <= (float)(H - 1));
        bool vx0 = (x0f >= 0.0f) && (x0f <= (float)(W - 1));
        bool vx1 = (x1f >= 0.0f) && (x1f <= (float)(W - 1));

        float w00 = (vy0 && vx0) ? wy0 * wx0 * m : 0.0f;
        float w01 = (vy0 && vx1) ? wy0 * wx1 * m : 0.0f;
        float w10 = (vy1 && vx0) ? wy1 * wx0 * m : 0.0f;
        float w11 = (vy1 && vx1) ? wy1 * wx1 * m : 0.0f;

        int yi0 = min(max((int)y0f, 0), H - 1);
        int yi1 = min(max((int)y1f, 0), H - 1);
        int xi0 = min(max((int)x0f, 0), W - 1);
        int xi1 = min(max((int)x1f, 0), W - 1);

        uint32_t base = (uint32_t)((yi0 * W + xi0) * C);
        uint32_t d = (uint32_t)((xi1 - xi0) * C) |
                     ((uint32_t)((yi1 - yi0) * W * C) << 16);

        int gi = (blk * 128 + p) * 9 + t;
        g_gw[gi] = make_float4(w00, w01, w10, w11);
        g_gd[gi] = make_uint2(base, d);
    }
}

// ---------------------------------------------------------------------------
// Kernel 2: deformable gather (params staged in smem) + mma.sync GEMM.
// 512 threads (16 warps), warp grid 4M x 4N, warp tile 32x16.
// Block = half-row: M=128 oc x N=64 pos, K=576. grid = B*HO*2 = 2048.
// smem: B db 16KB + params 13.5KB.
// ---------------------------------------------------------------------------
__global__ void __launch_bounds__(512, 2)
deform_mma_kernel(const float* __restrict__ bias, float* __restrict__ out) {
    extern __shared__ char smraw[];
    char* smb = (char*)(((uintptr_t)smraw + 1023) & ~(uintptr_t)1023);
    char* smB[2] = {smb, smb + 8192};
    float4* spW = (float4*)(smb + 16384);           // [64*9]
    uint2*  spD = (uint2*)(smb + 16384 + 9216);     // [64*9]

    int tid   = threadIdx.x;
    int warp  = tid >> 5;
    int lane  = tid & 31;
    int warpM = warp >> 2;   // 0..3
    int warpN = warp & 3;    // 0..3

    int blk  = blockIdx.x;   // ((b*128+h)*2 + half)
    int row  = blk >> 1;
    int b    = row >> 7;
    int h    = row & 127;
    int w0   = (blk & 1) * 64;

    int q  = lane >> 3;
    int rr = lane & 7;
    int bRow  = warpN * 16 + (q >> 1) * 8 + rr;
    int bKoff = (q & 1) * 16;

    float acc[2][2][4];
#pragma unroll
    for (int mi = 0; mi < 2; mi++)
#pragma unroll
        for (int ni = 0; ni < 2; ni++)
#pragma unroll
            for (int e = 0; e < 4; e++) acc[mi][ni][e] = 0.0f;

    const float* xt = g_xt + (size_t)b * (H * W * C);
    int cch = lane * 2;
    int gbase = (row * 128 + w0) * 9;

    // ---- stage all 576 params for this block into smem ----
    for (int j = tid; j < 576; j += 512) {
        spW[j] = g_gw[gbase + j];
        spD[j] = g_gd[gbase + j];
    }
    __syncthreads();

    auto gatherTap = [&](int t, char* dstB) {
#pragma unroll
        for (int i = 0; i < 4; i++) {
            int p  = warp * 4 + i;
            float4 w = spW[p * 9 + t];
            uint2 dd = spD[p * 9 + t];
            const float* base = xt + dd.x + cch;
            uint32_t dx = dd.y & 0xffffu;
            uint32_t dy = dd.y >> 16;
            float2 f00 = *(const float2*)(base);
            float2 f01 = *(const float2*)(base + dx);
            float2 f10 = *(const float2*)(base + dy);
            float2 f11 = *(const float2*)(base + dx + dy);
            float r0 = w.x * f00.x + w.y * f01.x + w.z * f10.x + w.w * f11.x;
            float r1 = w.x * f00.y + w.y * f01.y + w.z * f10.y + w.w * f11.y;
            __half2 hv = __floats2half2_rn(r0, r1);
            *(uint32_t*)(dstB + sw128((uint32_t)(p * 128 + lane * 4))) =
                *(uint32_t*)&hv;
        }
    };

    gatherTap(0, smB[0]);
    __syncthreads();

    for (int t = 0; t < 9; t++) {
        int cur = t & 1;
        uint32_t bB = smem_u32(smB[cur]);

        // prefetch next tap's B while MMA runs on current
        if (t < 8) gatherTap(t + 1, smB[cur ^ 1]);

#pragma unroll
        for (int ks = 0; ks < 4; ks++) {
            uint32_t a[2][4];
#pragma unroll
            for (int mi = 0; mi < 2; mi++) {
                uint4 f = g_wfM[((t * 4 + ks) * 8 + warpM * 2 + mi) * 32 + lane];
                a[mi][0] = f.x; a[mi][1] = f.y; a[mi][2] = f.z; a[mi][3] = f.w;
            }
            uint32_t bf[2][2];
            {
                uint32_t addr = bB +
                    sw128((uint32_t)(bRow * 128 + ks * 32 + bKoff));
                uint32_t r0, r1, r2, r3;
                LDMX4(r0, r1, r2, r3, addr);
                bf[0][0] = r0; bf[0][1] = r1;
                bf[1][0] = r2; bf[1][1] = r3;
            }
#pragma unroll
            for (int mi = 0; mi < 2; mi++)
#pragma unroll
                for (int ni = 0; ni < 2; ni++)
                    HMMA(acc[mi][ni], a[mi], bf[ni]);
        }
        __syncthreads();
    }

    // ---- epilogue ----
#pragma unroll
    for (int mi = 0; mi < 2; mi++) {
        int oc0 = warpM * 32 + mi * 16 + (lane >> 2);
        float bv0 = bias[oc0];
        float bv1 = bias[oc0 + 8];
        float* row0 = out + (((size_t)b * OCH + oc0) * HO + h) * WO + w0;
        float* row1 = row0 + 8 * (HO * WO);
#pragma unroll
        for (int ni = 0; ni < 2; ni++) {
            int n = warpN * 16 + ni * 8 + (lane & 3) * 2;
            *(float2*)(row0 + n) =
                make_float2(acc[mi][ni][0] + bv0, acc[mi][ni][1] + bv0);
            *(float2*)(row1 + n) =
                make_float2(acc[mi][ni][2] + bv1, acc[mi][ni][3] + bv1);
        }
    }
}

// ---------------------------------------------------------------------------
extern "C" void kernel_launch(void* const* d_in, const int* in_sizes, int n_in,
                              void* d_out, int out_size) {
    const float* x    = (const float*)d_in[0];
    const float* ow   = (const float*)d_in[1];
    const float* ob   = (const float*)d_in[2];
    const float* wt   = (const float*)d_in[3];
    const float* bias = (const float*)d_in[4];
    float* out = (float*)d_out;

    int offSmem  = 32768 + 1024;
    int mainSmem = 16384 + 13824 + 1024;
    cudaFuncSetAttribute(offset_mma_kernel,
                         cudaFuncAttributeMaxDynamicSharedMemorySize, offSmem);
    cudaFuncSetAttribute(deform_mma_kernel,
                         cudaFuncAttributeMaxDynamicSharedMemorySize, mainSmem);

    dim3 tb(32, 8);
    dim3 tg((H * W) / 32, 1, B);
    transpose_kernel<<<tg, tb>>>(x);

    wfragM_kernel<<<(9 * 4 * 8 * 32 + 255) / 256, 256>>>(wt);
    wfragO_kernel<<<(9 * 4 * 2 * 32 + 255) / 256, 256>>>(ow);

    offset_mma_kernel<<<B * HO, 512, offSmem>>>(ob);

    deform_mma_kernel<<<B * HO * 2, 512, mainSmem>>>(bias, out);
}

// round 12
// speedup vs baseline: 1.0250x; 1.0250x over previous
#include <cuda_runtime.h>
#include <cuda_fp16.h>
#include <math.h>
#include <stdint.h>

#define B 8
#define C 64
#define H 256
#define W 256
#define OCH 128
#define K2 9
#define HO 128
#define WO 128
#define CK 576

// ---------------- device scratch (allocation-free) ----------------
__device__ __align__(16) float g_xt[B * H * W * C];    // x NHWC fp32
__device__ __align__(16) uint4 g_wfM[9 * 4 * 8 * 32];  // main A frags [t][ks][f][lane]
__device__ __align__(16) uint4 g_wfOh[9 * 4 * 2 * 32]; // offset A frags hi
__device__ __align__(16) uint4 g_wfOl[9 * 4 * 2 * 32]; // offset A frags lo

__device__ __forceinline__ uint32_t smem_u32(const void* p) {
    uint32_t a;
    asm("{ .reg .u64 t; cvta.to.shared.u64 t, %1; cvt.u32.u64 %0, t; }"
        : "=r"(a) : "l"(p));
    return a;
}
__device__ __forceinline__ uint32_t sw128(uint32_t off) {
    return off ^ ((off >> 3) & 0x70);
}
__device__ __forceinline__ uint32_t pack_h2(float a, float b) {
    __half2 t = __floats2half2_rn(a, b);
    return *(uint32_t*)&t;
}
#define LDMX4(r0, r1, r2, r3, addr)                                          \
    asm volatile("ldmatrix.sync.aligned.m8n8.x4.shared.b16 {%0,%1,%2,%3}, [%4];" \
                 : "=r"(r0), "=r"(r1), "=r"(r2), "=r"(r3) : "r"(addr))
#define HMMA(acc, a, b)                                                       \
    asm volatile(                                                             \
        "mma.sync.aligned.m16n8k16.row.col.f32.f16.f16.f32 "                  \
        "{%0,%1,%2,%3}, {%4,%5,%6,%7}, {%8,%9}, {%0,%1,%2,%3};"               \
        : "+f"(acc[0]), "+f"(acc[1]), "+f"(acc[2]), "+f"(acc[3])              \
        : "r"(a[0]), "r"(a[1]), "r"(a[2]), "r"(a[3]), "r"(b[0]), "r"(b[1]))

// ---------------------------------------------------------------------------
// Kernel 0: NCHW fp32 -> NHWC fp32
// ---------------------------------------------------------------------------
__global__ void transpose_kernel(const float* __restrict__ x) {
    __shared__ float tile[64][33];
    int b  = blockIdx.z;
    int s0 = blockIdx.x * 32;
    int tx = threadIdx.x, ty = threadIdx.y;
    const float* xb = x + (size_t)b * (C * H * W);
#pragma unroll
    for (int cy = ty; cy < 64; cy += 8)
        tile[cy][tx] = xb[(size_t)cy * (H * W) + s0 + tx];
    __syncthreads();
    size_t obase = (size_t)b * (H * W * C);
#pragma unroll
    for (int pp = 0; pp < 4; pp++) {
        int p = ty + pp * 8;
        float2 v = make_float2(tile[2 * tx][p], tile[2 * tx + 1][p]);
        *(float2*)(g_xt + obase + (size_t)(s0 + p) * C + 2 * tx) = v;
    }
}

// ---------------------------------------------------------------------------
// Kernel 0b: main weights -> A fragments
// ---------------------------------------------------------------------------
__global__ void wfragM_kernel(const float* __restrict__ wt) {
    int j = blockIdx.x * 256 + threadIdx.x;
    if (j >= 9 * 4 * 8 * 32) return;
    int lane = j & 31;
    int f    = (j >> 5) & 7;
    int ks   = (j >> 8) & 3;
    int t    = j >> 10;
    int r  = lane >> 2;
    int c2 = lane & 3;
    int oc0 = f * 16 + r;
    int ch0 = ks * 16 + c2 * 2;
#define WV(oc, ch) wt[(oc) * CK + (ch) * 9 + t]
    uint4 o;
    o.x = pack_h2(WV(oc0, ch0),         WV(oc0, ch0 + 1));
    o.y = pack_h2(WV(oc0 + 8, ch0),     WV(oc0 + 8, ch0 + 1));
    o.z = pack_h2(WV(oc0, ch0 + 8),     WV(oc0, ch0 + 9));
    o.w = pack_h2(WV(oc0 + 8, ch0 + 8), WV(oc0 + 8, ch0 + 9));
#undef WV
    g_wfM[j] = o;
}

// ---------------------------------------------------------------------------
// Kernel 0c: offset weights -> A fragments hi/lo (M=32, rows>=27 zero)
// ---------------------------------------------------------------------------
__global__ void wfragO_kernel(const float* __restrict__ ow) {
    int j = blockIdx.x * 256 + threadIdx.x;
    if (j >= 9 * 4 * 2 * 32) return;
    int lane = j & 31;
    int mi   = (j >> 5) & 1;
    int ks   = (j >> 6) & 3;
    int t    = j >> 8;
    int r  = lane >> 2;
    int c2 = lane & 3;
    int oc0 = mi * 16 + r;
    int ch0 = ks * 16 + c2 * 2;

    float v[2][2][2];
#pragma unroll
    for (int rh = 0; rh < 2; rh++)
#pragma unroll
        for (int chh = 0; chh < 2; chh++)
#pragma unroll
            for (int e = 0; e < 2; e++) {
                int oc = oc0 + rh * 8;
                int ch = ch0 + chh * 8 + e;
                v[rh][chh][e] = (oc < 27) ? ow[(oc * 64 + ch) * 9 + t] : 0.0f;
            }
    uint4 oh, ol;
#define SPLIT(dsth, dstl, a, b)                                              \
    {                                                                         \
        __half2 hh = __floats2half2_rn(a, b);                                 \
        float2 hf = __half22float2(hh);                                       \
        dsth = *(uint32_t*)&hh;                                               \
        __half2 lls = __floats2half2_rn((a) - hf.x, (b) - hf.y);              \
        dstl = *(uint32_t*)&lls;                                              \
    }
    SPLIT(oh.x, ol.x, v[0][0][0], v[0][0][1]);
    SPLIT(oh.y, ol.y, v[1][0][0], v[1][0][1]);
    SPLIT(oh.z, ol.z, v[0][1][0], v[0][1][1]);
    SPLIT(oh.w, ol.w, v[1][1][0], v[1][1][1]);
#undef SPLIT
    g_wfOh[j] = oh;
    g_wfOl[j] = ol;
}

// ---------------------------------------------------------------------------
// FUSED kernel: offset conv (phase 1) + param precompute + main GEMM (phase 2)
// Block = (b,h). 256 threads. grid = B*HO = 1024.
// smem: [0,16K) Bh / phase2 B db   [16K,32K) Bl / smOff
//       [32K,50.25K) spW float4[128*9]   [50.25K,59.25K) spD uint2[128*9]
// ---------------------------------------------------------------------------
__global__ void __launch_bounds__(256, 3)
fused_kernel(const float* __restrict__ ob, const float* __restrict__ bias,
             float* __restrict__ out) {
    extern __shared__ char smraw[];
    char* smb = (char*)(((uintptr_t)smraw + 1023) & ~(uintptr_t)1023);
    char* Bh = smb;                       // 16KB (phase1), B db (phase2)
    char* Bl = smb + 16384;               // 16KB (phase1), smOff (epilogue)
    float4* spW = (float4*)(smb + 32768); // 18432 B
    uint2*  spD = (uint2*)(smb + 32768 + 18432); // 9216 B

    int tid  = threadIdx.x;
    int warp = tid >> 5;
    int lane = tid & 31;

    int blk = blockIdx.x;   // b*128 + h
    int b   = blk >> 7;
    int h   = blk & 127;

    size_t xbase = (size_t)b * (H * W * C);
    const float* xt = g_xt + xbase;
    int cch = lane * 2;

    // ====================== PHASE 1: offset conv ======================
    {
        int q  = lane >> 3;
        int rr = lane & 7;
        int bRowB = warp * 16 + (q >> 1) * 8 + rr;
        int bKoff = (q & 1) * 16;

        float acc[2][2][4];
#pragma unroll
        for (int mi = 0; mi < 2; mi++)
#pragma unroll
            for (int ni = 0; ni < 2; ni++)
#pragma unroll
                for (int e = 0; e < 4; e++) acc[mi][ni][e] = 0.0f;

        uint32_t bhB = smem_u32(Bh);
        uint32_t blB = smem_u32(Bl);

        for (int t = 0; t < 9; t++) {
            // ---- gather tap t (strided row read, zero-padded) ----
            {
                int ky = t / 3;
                int kx = t - ky * 3;
                int iy = 2 * h - 1 + ky;
                bool yok = (iy >= 0) && (iy < H);
                const float* rowb = xt + (size_t)iy * (W * C) + cch;
#pragma unroll
                for (int i = 0; i < 16; i++) {
                    int p  = warp * 16 + i;
                    int ix = 2 * p - 1 + kx;
                    float2 v = make_float2(0.0f, 0.0f);
                    if (yok && ix >= 0 && ix < W)
                        v = *(const float2*)(rowb + (size_t)ix * C);
                    __half2 hh = __floats2half2_rn(v.x, v.y);
                    float2 hf = __half22float2(hh);
                    __half2 ll = __floats2half2_rn(v.x - hf.x, v.y - hf.y);
                    uint32_t so = sw128((uint32_t)(p * 128 + lane * 4));
                    *(uint32_t*)(Bh + so) = *(uint32_t*)&hh;
                    *(uint32_t*)(Bl + so) = *(uint32_t*)&ll;
                }
            }
            __syncthreads();

#pragma unroll
            for (int ks = 0; ks < 4; ks++) {
                uint32_t ah[2][4], al[2][4], bh2[2][2], bl2[2][2];
#pragma unroll
                for (int mi = 0; mi < 2; mi++) {
                    uint4 fh = g_wfOh[((t * 4 + ks) * 2 + mi) * 32 + lane];
                    uint4 fl = g_wfOl[((t * 4 + ks) * 2 + mi) * 32 + lane];
                    ah[mi][0] = fh.x; ah[mi][1] = fh.y; ah[mi][2] = fh.z; ah[mi][3] = fh.w;
                    al[mi][0] = fl.x; al[mi][1] = fl.y; al[mi][2] = fl.z; al[mi][3] = fl.w;
                }
                {
                    uint32_t boff = sw128((uint32_t)(bRowB * 128 + ks * 32 + bKoff));
                    uint32_t r0, r1, r2, r3;
                    LDMX4(r0, r1, r2, r3, bhB + boff);
                    bh2[0][0] = r0; bh2[0][1] = r1; bh2[1][0] = r2; bh2[1][1] = r3;
                    LDMX4(r0, r1, r2, r3, blB + boff);
                    bl2[0][0] = r0; bl2[0][1] = r1; bl2[1][0] = r2; bl2[1][1] = r3;
                }
#pragma unroll
                for (int mi = 0; mi < 2; mi++)
#pragma unroll
                    for (int ni = 0; ni < 2; ni++) {
                        HMMA(acc[mi][ni], ah[mi], bh2[ni]);
                        HMMA(acc[mi][ni], ah[mi], bl2[ni]);
                        HMMA(acc[mi][ni], al[mi], bh2[ni]);
                    }
            }
            __syncthreads();
        }

        // ---- epilogue: offsets -> smOff (Bl region) ----
        float* smOff = (float*)Bl;  // [128][32]
        {
            int ocb  = lane >> 2;
            int posb = warp * 16 + (lane & 3) * 2;
#pragma unroll
            for (int mi = 0; mi < 2; mi++) {
#pragma unroll
                for (int eh = 0; eh < 2; eh++) {
                    int oc = mi * 16 + eh * 8 + ocb;
                    if (oc >= 27) continue;
                    float bv = ob[oc];
                    bool sig = (oc >= 18);
#pragma unroll
                    for (int ni = 0; ni < 2; ni++) {
#pragma unroll
                        for (int e0 = 0; e0 < 2; e0++) {
                            float v = acc[mi][ni][eh * 2 + e0] + bv;
                            if (sig) v = 1.0f / (1.0f + __expf(-v));
                            int pos = posb + ni * 8 + e0;
                            smOff[pos * 32 + oc] = v;
                        }
                    }
                }
            }
        }
        __syncthreads();

        // ---- param phase: 1152 (p,t) items -> spW/spD in smem ----
        float hyf = (float)(2 * h - 1);
        for (int j = tid; j < 128 * 9; j += 256) {
            int p = j / 9;
            int t = j - p * 9;
            float offx = smOff[p * 32 + t];
            float offy = smOff[p * 32 + 9 + t];
            float m    = smOff[p * 32 + 18 + t];

            float py = offy + (float)(t / 3) + hyf;
            float px = offx + (float)(t - (t / 3) * 3) + (float)(2 * p - 1);

            float y0f = floorf(py), x0f = floorf(px);
            float y1f = y0f + 1.0f, x1f = x0f + 1.0f;
            float wy1 = py - y0f, wy0 = 1.0f - wy1;
            float wx1 = px - x0f, wx0 = 1.0f - wx1;

            bool vy0 = (y0f >= 0.0f) && (y0f <= (float)(H - 1));
            bool vy1 = (y1f >= 0.0f) && (y1f <= (float)(H - 1));
            bool vx0 = (x0f >= 0.0f) && (x0f <= (float)(W - 1));
            bool vx1 = (x1f >= 0.0f) && (x1f <= (float)(W - 1));

            float w00 = (vy0 && vx0) ? wy0 * wx0 * m : 0.0f;
            float w01 = (vy0 && vx1) ? wy0 * wx1 * m : 0.0f;
            float w10 = (vy1 && vx0) ? wy1 * wx0 * m : 0.0f;
            float w11 = (vy1 && vx1) ? wy1 * wx1 * m : 0.0f;

            int yi0 = min(max((int)y0f, 0), H - 1);
            int yi1 = min(max((int)y1f, 0), H - 1);
            int xi0 = min(max((int)x0f, 0), W - 1);
            int xi1 = min(max((int)x1f, 0), W - 1);

            uint32_t base = (uint32_t)((yi0 * W + xi0) * C);
            uint32_t d = (uint32_t)((xi1 - xi0) * C) |
                         ((uint32_t)((yi1 - yi0) * W * C) << 16);

            spW[j] = make_float4(w00, w01, w10, w11);
            spD[j] = make_uint2(base, d);
        }
        __syncthreads();
    }

    // ====================== PHASE 2: main GEMM (two N=64 halves) =============
    {
        int warpM = warp >> 1;   // 0..3
        int warpN = warp & 1;    // 0..1
        int q  = lane >> 3;
        int rr = lane & 7;
        int bRow  = warpN * 32 + (q >> 1) * 8 + rr;
        int bKoff = (q & 1) * 16;

        char* smB[2] = {Bh, Bh + 8192};

        for (int half = 0; half < 2; half++) {
            int w0 = half * 64;

            float acc[2][4][4];
#pragma unroll
            for (int mi = 0; mi < 2; mi++)
#pragma unroll
                for (int ni = 0; ni < 4; ni++)
#pragma unroll
                    for (int e = 0; e < 4; e++) acc[mi][ni][e] = 0.0f;

            auto gatherTap = [&](int t, char* dstB) {
#pragma unroll
                for (int i = 0; i < 8; i++) {
                    int p  = warp * 8 + i;            // 0..63 within half
                    int pj = (w0 + p) * 9 + t;
                    float4 w = spW[pj];
                    uint2 dd = spD[pj];
                    const float* base = xt + dd.x + cch;
                    uint32_t dx = dd.y & 0xffffu;
                    uint32_t dy = dd.y >> 16;
                    float2 f00 = *(const float2*)(base);
                    float2 f01 = *(const float2*)(base + dx);
                    float2 f10 = *(const float2*)(base + dy);
                    float2 f11 = *(const float2*)(base + dx + dy);
                    float r0 = w.x * f00.x + w.y * f01.x + w.z * f10.x + w.w * f11.x;
                    float r1 = w.x * f00.y + w.y * f01.y + w.z * f10.y + w.w * f11.y;
                    __half2 hv = __floats2half2_rn(r0, r1);
                    *(uint32_t*)(dstB + sw128((uint32_t)(p * 128 + lane * 4))) =
                        *(uint32_t*)&hv;
                }
            };

            gatherTap(0, smB[0]);
            __syncthreads();

            for (int t = 0; t < 9; t++) {
                int cur = t & 1;
                uint32_t bB = smem_u32(smB[cur]);

                if (t < 8) gatherTap(t + 1, smB[cur ^ 1]);

#pragma unroll
                for (int ks = 0; ks < 4; ks++) {
                    uint32_t a[2][4];
#pragma unroll
                    for (int mi = 0; mi < 2; mi++) {
                        uint4 f = g_wfM[((t * 4 + ks) * 8 + warpM * 2 + mi) * 32 + lane];
                        a[mi][0] = f.x; a[mi][1] = f.y; a[mi][2] = f.z; a[mi][3] = f.w;
                    }
                    uint32_t bf[4][2];
#pragma unroll
                    for (int j2 = 0; j2 < 2; j2++) {
                        uint32_t addr = bB +
                            sw128((uint32_t)((bRow + j2 * 16) * 128 + ks * 32 + bKoff));
                        uint32_t r0, r1, r2, r3;
                        LDMX4(r0, r1, r2, r3, addr);
                        bf[j2 * 2 + 0][0] = r0; bf[j2 * 2 + 0][1] = r1;
                        bf[j2 * 2 + 1][0] = r2; bf[j2 * 2 + 1][1] = r3;
                    }
#pragma unroll
                    for (int mi = 0; mi < 2; mi++)
#pragma unroll
                        for (int ni = 0; ni < 4; ni++)
                            HMMA(acc[mi][ni], a[mi], bf[ni]);
                }
                __syncthreads();
            }

            // ---- epilogue for this half ----
#pragma unroll
            for (int mi = 0; mi < 2; mi++) {
                int oc0 = warpM * 32 + mi * 16 + (lane >> 2);
                float bv0 = bias[oc0];
                float bv1 = bias[oc0 + 8];
                float* row0 = out + (((size_t)b * OCH + oc0) * HO + h) * WO + w0;
                float* row1 = row0 + 8 * (HO * WO);
#pragma unroll
                for (int ni = 0; ni < 4; ni++) {
                    int n = warpN * 32 + ni * 8 + (lane & 3) * 2;
                    *(float2*)(row0 + n) =
                        make_float2(acc[mi][ni][0] + bv0, acc[mi][ni][1] + bv0);
                    *(float2*)(row1 + n) =
                        make_float2(acc[mi][ni][2] + bv1, acc[mi][ni][3] + bv1);
                }
            }
        }
    }
}

// ---------------------------------------------------------------------------
extern "C" void kernel_launch(void* const* d_in, const int* in_sizes, int n_in,
                              void* d_out, int out_size) {
    const float* x    = (const float*)d_in[0];
    const float* ow   = (const float*)d_in[1];
    const float* ob   = (const float*)d_in[2];
    const float* wt   = (const float*)d_in[3];
    const float* bias = (const float*)d_in[4];
    float* out = (float*)d_out;

    int fusedSmem = 32768 + 18432 + 9216 + 1024;   // 61440
    cudaFuncSetAttribute(fused_kernel,
                         cudaFuncAttributeMaxDynamicSharedMemorySize, fusedSmem);

    dim3 tb(32, 8);
    dim3 tg((H * W) / 32, 1, B);
    transpose_kernel<<<tg, tb>>>(x);

    wfragM_kernel<<<(9 * 4 * 8 * 32 + 255) / 256, 256>>>(wt);
    wfragO_kernel<<<(9 * 4 * 2 * 32 + 255) / 256, 256>>>(ow);

    fused_kernel<<<B * HO, 256, fusedSmem>>>(ob, bias, out);
}

// round 13
// speedup vs baseline: 1.0288x; 1.0037x over previous
#include <cuda_runtime.h>
#include <cuda_fp16.h>
#include <math.h>
#include <stdint.h>

#define B 8
#define C 64
#define H 256
#define W 256
#define OCH 128
#define K2 9
#define HO 128
#define WO 128
#define CK 576

// ---------------- device scratch (allocation-free) ----------------
__device__ __align__(16) float g_xt[B * H * W * C];    // x NHWC fp32
__device__ __align__(16) uint4 g_wfM[9 * 4 * 8 * 32];  // main A frags [t][ks][f][lane]
__device__ __align__(16) uint4 g_wfOh[9 * 4 * 2 * 32]; // offset A frags hi
__device__ __align__(16) uint4 g_wfOl[9 * 4 * 2 * 32]; // offset A frags lo
__device__ __align__(16) float4 g_gw[B * HO * WO * 9]; // bilinear weights (mask folded)
__device__ __align__(16) uint2  g_gd[B * HO * WO * 9]; // base elem idx, (dx | dy<<16)

__device__ __forceinline__ uint32_t smem_u32(const void* p) {
    uint32_t a;
    asm("{ .reg .u64 t; cvta.to.shared.u64 t, %1; cvt.u32.u64 %0, t; }"
        : "=r"(a) : "l"(p));
    return a;
}
__device__ __forceinline__ uint32_t sw128(uint32_t off) {
    return off ^ ((off >> 3) & 0x70);
}
__device__ __forceinline__ uint32_t pack_h2(float a, float b) {
    __half2 t = __floats2half2_rn(a, b);
    return *(uint32_t*)&t;
}
#define LDMX4(r0, r1, r2, r3, addr)                                          \
    asm volatile("ldmatrix.sync.aligned.m8n8.x4.shared.b16 {%0,%1,%2,%3}, [%4];" \
                 : "=r"(r0), "=r"(r1), "=r"(r2), "=r"(r3) : "r"(addr))
#define HMMA(acc, a, b)                                                       \
    asm volatile(                                                             \
        "mma.sync.aligned.m16n8k16.row.col.f32.f16.f16.f32 "                  \
        "{%0,%1,%2,%3}, {%4,%5,%6,%7}, {%8,%9}, {%0,%1,%2,%3};"               \
        : "+f"(acc[0]), "+f"(acc[1]), "+f"(acc[2]), "+f"(acc[3])              \
        : "r"(a[0]), "r"(a[1]), "r"(a[2]), "r"(a[3]), "r"(b[0]), "r"(b[1]))
#define BAR_SYNC(id, cnt)                                                     \
    asm volatile("bar.sync %0, %1;" :: "r"(id), "r"(cnt) : "memory")
#define BAR_ARRIVE(id, cnt)                                                   \
    asm volatile("bar.arrive %0, %1;" :: "r"(id), "r"(cnt) : "memory")

// ---------------------------------------------------------------------------
// Kernel 0: NCHW fp32 -> NHWC fp32
// ---------------------------------------------------------------------------
__global__ void transpose_kernel(const float* __restrict__ x) {
    __shared__ float tile[64][33];
    int b  = blockIdx.z;
    int s0 = blockIdx.x * 32;
    int tx = threadIdx.x, ty = threadIdx.y;
    const float* xb = x + (size_t)b * (C * H * W);
#pragma unroll
    for (int cy = ty; cy < 64; cy += 8)
        tile[cy][tx] = xb[(size_t)cy * (H * W) + s0 + tx];
    __syncthreads();
    size_t obase = (size_t)b * (H * W * C);
#pragma unroll
    for (int pp = 0; pp < 4; pp++) {
        int p = ty + pp * 8;
        float2 v = make_float2(tile[2 * tx][p], tile[2 * tx + 1][p]);
        *(float2*)(g_xt + obase + (size_t)(s0 + p) * C + 2 * tx) = v;
    }
}

// ---------------------------------------------------------------------------
// Kernel 0b: main weights -> A fragments
// ---------------------------------------------------------------------------
__global__ void wfragM_kernel(const float* __restrict__ wt) {
    int j = blockIdx.x * 256 + threadIdx.x;
    if (j >= 9 * 4 * 8 * 32) return;
    int lane = j & 31;
    int f    = (j >> 5) & 7;
    int ks   = (j >> 8) & 3;
    int t    = j >> 10;
    int r  = lane >> 2;
    int c2 = lane & 3;
    int oc0 = f * 16 + r;
    int ch0 = ks * 16 + c2 * 2;
#define WV(oc, ch) wt[(oc) * CK + (ch) * 9 + t]
    uint4 o;
    o.x = pack_h2(WV(oc0, ch0),         WV(oc0, ch0 + 1));
    o.y = pack_h2(WV(oc0 + 8, ch0),     WV(oc0 + 8, ch0 + 1));
    o.z = pack_h2(WV(oc0, ch0 + 8),     WV(oc0, ch0 + 9));
    o.w = pack_h2(WV(oc0 + 8, ch0 + 8), WV(oc0 + 8, ch0 + 9));
#undef WV
    g_wfM[j] = o;
}

// ---------------------------------------------------------------------------
// Kernel 0c: offset weights -> A fragments hi/lo (M=32, rows>=27 zero)
// ---------------------------------------------------------------------------
__global__ void wfragO_kernel(const float* __restrict__ ow) {
    int j = blockIdx.x * 256 + threadIdx.x;
    if (j >= 9 * 4 * 2 * 32) return;
    int lane = j & 31;
    int mi   = (j >> 5) & 1;
    int ks   = (j >> 6) & 3;
    int t    = j >> 8;
    int r  = lane >> 2;
    int c2 = lane & 3;
    int oc0 = mi * 16 + r;
    int ch0 = ks * 16 + c2 * 2;

    float v[2][2][2];
#pragma unroll
    for (int rh = 0; rh < 2; rh++)
#pragma unroll
        for (int chh = 0; chh < 2; chh++)
#pragma unroll
            for (int e = 0; e < 2; e++) {
                int oc = oc0 + rh * 8;
                int ch = ch0 + chh * 8 + e;
                v[rh][chh][e] = (oc < 27) ? ow[(oc * 64 + ch) * 9 + t] : 0.0f;
            }
    uint4 oh, ol;
#define SPLIT(dsth, dstl, a, b)                                              \
    {                                                                         \
        __half2 hh = __floats2half2_rn(a, b);                                 \
        float2 hf = __half22float2(hh);                                       \
        dsth = *(uint32_t*)&hh;                                               \
        __half2 lls = __floats2half2_rn((a) - hf.x, (b) - hf.y);              \
        dstl = *(uint32_t*)&lls;                                              \
    }
    SPLIT(oh.x, ol.x, v[0][0][0], v[0][0][1]);
    SPLIT(oh.y, ol.y, v[1][0][0], v[1][0][1]);
    SPLIT(oh.z, ol.z, v[0][1][0], v[0][1][1]);
    SPLIT(oh.w, ol.w, v[1][1][0], v[1][1][1]);
#undef SPLIT
    g_wfOh[j] = oh;
    g_wfOl[j] = ol;
}

// ---------------------------------------------------------------------------
// Kernel 1: offset conv via split-fp16 mma + fused bilinear-param precompute.
// (round-10 shape) Block = (b,h): M=32(27) x N=128. smem 32KB.
// ---------------------------------------------------------------------------
__global__ void __launch_bounds__(256, 4)
offset_mma_kernel(const float* __restrict__ ob) {
    extern __shared__ char smraw[];
    char* smb = (char*)(((uintptr_t)smraw + 1023) & ~(uintptr_t)1023);
    char* Bh = smb;
    char* Bl = smb + 16384;

    int tid  = threadIdx.x;
    int warp = tid >> 5;
    int lane = tid & 31;

    int blk = blockIdx.x;   // b*128 + h
    int b   = blk >> 7;
    int h   = blk & 127;

    int q  = lane >> 3;
    int rr = lane & 7;
    int bRowB = warp * 16 + (q >> 1) * 8 + rr;
    int bKoff = (q & 1) * 16;

    float acc[2][2][4];
#pragma unroll
    for (int mi = 0; mi < 2; mi++)
#pragma unroll
        for (int ni = 0; ni < 2; ni++)
#pragma unroll
            for (int e = 0; e < 4; e++) acc[mi][ni][e] = 0.0f;

    size_t xbase = (size_t)b * (H * W * C);
    int cch = lane * 2;
    uint32_t bhB = smem_u32(Bh);
    uint32_t blB = smem_u32(Bl);

    for (int t = 0; t < 9; t++) {
        {
            int ky = t / 3;
            int kx = t - ky * 3;
            int iy = 2 * h - 1 + ky;
            bool yok = (iy >= 0) && (iy < H);
            const float* rowb = g_xt + xbase + (size_t)iy * (W * C) + cch;
#pragma unroll
            for (int i = 0; i < 16; i++) {
                int p  = warp * 16 + i;
                int ix = 2 * p - 1 + kx;
                float2 v = make_float2(0.0f, 0.0f);
                if (yok && ix >= 0 && ix < W)
                    v = *(const float2*)(rowb + (size_t)ix * C);
                __half2 hh = __floats2half2_rn(v.x, v.y);
                float2 hf = __half22float2(hh);
                __half2 ll = __floats2half2_rn(v.x - hf.x, v.y - hf.y);
                uint32_t so = sw128((uint32_t)(p * 128 + lane * 4));
                *(uint32_t*)(Bh + so) = *(uint32_t*)&hh;
                *(uint32_t*)(Bl + so) = *(uint32_t*)&ll;
            }
        }
        __syncthreads();

#pragma unroll
        for (int ks = 0; ks < 4; ks++) {
            uint32_t ah[2][4], al[2][4], bh[2][2], bl[2][2];
#pragma unroll
            for (int mi = 0; mi < 2; mi++) {
                uint4 fh = g_wfOh[((t * 4 + ks) * 2 + mi) * 32 + lane];
                uint4 fl = g_wfOl[((t * 4 + ks) * 2 + mi) * 32 + lane];
                ah[mi][0] = fh.x; ah[mi][1] = fh.y; ah[mi][2] = fh.z; ah[mi][3] = fh.w;
                al[mi][0] = fl.x; al[mi][1] = fl.y; al[mi][2] = fl.z; al[mi][3] = fl.w;
            }
            {
                uint32_t boff = sw128((uint32_t)(bRowB * 128 + ks * 32 + bKoff));
                uint32_t r0, r1, r2, r3;
                LDMX4(r0, r1, r2, r3, bhB + boff);
                bh[0][0] = r0; bh[0][1] = r1; bh[1][0] = r2; bh[1][1] = r3;
                LDMX4(r0, r1, r2, r3, blB + boff);
                bl[0][0] = r0; bl[0][1] = r1; bl[1][0] = r2; bl[1][1] = r3;
            }
#pragma unroll
            for (int mi = 0; mi < 2; mi++)
#pragma unroll
                for (int ni = 0; ni < 2; ni++) {
                    HMMA(acc[mi][ni], ah[mi], bh[ni]);
                    HMMA(acc[mi][ni], ah[mi], bl[ni]);
                    HMMA(acc[mi][ni], al[mi], bh[ni]);
                }
        }
        __syncthreads();
    }

    float* smOff = (float*)Bh;  // [128][32]
    {
        int ocb  = lane >> 2;
        int posb = warp * 16 + (lane & 3) * 2;
#pragma unroll
        for (int mi = 0; mi < 2; mi++) {
#pragma unroll
            for (int eh = 0; eh < 2; eh++) {
                int oc = mi * 16 + eh * 8 + ocb;
                if (oc >= 27) continue;
                float bv = ob[oc];
                bool sig = (oc >= 18);
#pragma unroll
                for (int ni = 0; ni < 2; ni++) {
#pragma unroll
                    for (int e0 = 0; e0 < 2; e0++) {
                        float v = acc[mi][ni][eh * 2 + e0] + bv;
                        if (sig) v = 1.0f / (1.0f + __expf(-v));
                        int pos = posb + ni * 8 + e0;
                        smOff[pos * 32 + oc] = v;
                    }
                }
            }
        }
    }
    __syncthreads();

    float hyf = (float)(2 * h - 1);
    for (int j = tid; j < 128 * 9; j += 256) {
        int p = j / 9;
        int t = j - p * 9;
        float offx = smOff[p * 32 + t];
        float offy = smOff[p * 32 + 9 + t];
        float m    = smOff[p * 32 + 18 + t];

        float py = offy + (float)(t / 3) + hyf;
        float px = offx + (float)(t - (t / 3) * 3) + (float)(2 * p - 1);

        float y0f = floorf(py), x0f = floorf(px);
        float y1f = y0f + 1.0f, x1f = x0f + 1.0f;
        float wy1 = py - y0f, wy0 = 1.0f - wy1;
        float wx1 = px - x0f, wx0 = 1.0f - wx1;

        bool vy0 = (y0f >= 0.0f) && (y0f <= (float)(H - 1));
        bool vy1 = (y1f >= 0.0f) && (y1f <= (float)(H - 1));
        bool vx0 = (x0f >= 0.0f) && (x0f <= (float)(W - 1));
        bool vx1 = (x1f >= 0.0f) && (x1f <= (float)(W - 1));

        float w00 = (vy0 && vx0) ? wy0 * wx0 * m : 0.0f;
        float w01 = (vy0 && vx1) ? wy0 * wx1 * m : 0.0f;
        float w10 = (vy1 && vx0) ? wy1 * wx0 * m : 0.0f;
        float w11 = (vy1 && vx1) ? wy1 * wx1 * m : 0.0f;

        int yi0 = min(max((int)y0f, 0), H - 1);
        int yi1 = min(max((int)y1f, 0), H - 1);
        int xi0 = min(max((int)x0f, 0), W - 1);
        int xi1 = min(max((int)x1f, 0), W - 1);

        uint32_t base = (uint32_t)((yi0 * W + xi0) * C);
        uint32_t d = (uint32_t)((xi1 - xi0) * C) |
                     ((uint32_t)((yi1 - yi0) * W * C) << 16);

        int gi = (blk * 128 + p) * 9 + t;
        g_gw[gi] = make_float4(w00, w01, w10, w11);
        g_gd[gi] = make_uint2(base, d);
    }
}

// ---------------------------------------------------------------------------
// Kernel 2: WARP-SPECIALIZED deformable gather + mma GEMM.
// 512 threads: warps 0-7 consumers (4M x 2N, tile 32x32), warps 8-15 producers.
// Block = half-row: M=128 oc x N=64 pos, K=576. grid = B*HO*2 = 2048.
// smem: B ring 4 x 8KB = 32KB @0; params spW 9216 + spD 4608 @32768.
// Named barriers: FULL_s = 1+s, FREE_s = 5+s, count 512.
// ---------------------------------------------------------------------------
__global__ void __launch_bounds__(512, 2)
deform_mma_kernel(const float* __restrict__ bias, float* __restrict__ out) {
    extern __shared__ char smraw[];
    char* smb = (char*)(((uintptr_t)smraw + 1023) & ~(uintptr_t)1023);
    char* ring = smb;                               // 4 x 8KB
    float4* spW = (float4*)(smb + 32768);           // [64*9]
    uint2*  spD = (uint2*)(smb + 32768 + 9216);     // [64*9]

    int tid   = threadIdx.x;
    int warp  = tid >> 5;
    int lane  = tid & 31;

    int blk  = blockIdx.x;   // ((b*128+h)*2 + half)
    int row  = blk >> 1;
    int b    = row >> 7;
    int h    = row & 127;
    int w0   = (blk & 1) * 64;

    const float* xt = g_xt + (size_t)b * (H * W * C);
    int cch = lane * 2;
    int gbase = (row * 128 + w0) * 9;

    // ---- stage params (all 512 threads) ----
    for (int j = tid; j < 576; j += 512) {
        spW[j] = g_gw[gbase + j];
        spD[j] = g_gd[gbase + j];
    }
    __syncthreads();

    if (warp >= 8) {
        // =================== PRODUCERS ===================
        int pw = warp - 8;    // 0..7, 8 positions each
        for (int t = 0; t < 9; t++) {
            int s = t & 3;
            if (t >= 4) BAR_SYNC(5 + s, 512);
            char* dstB = ring + s * 8192;
#pragma unroll
            for (int i = 0; i < 8; i++) {
                int p  = pw * 8 + i;
                float4 w = spW[p * 9 + t];
                uint2 dd = spD[p * 9 + t];
                const float* base = xt + dd.x + cch;
                uint32_t dx = dd.y & 0xffffu;
                uint32_t dy = dd.y >> 16;
                float2 f00 = *(const float2*)(base);
                float2 f01 = *(const float2*)(base + dx);
                float2 f10 = *(const float2*)(base + dy);
                float2 f11 = *(const float2*)(base + dx + dy);
                float r0 = w.x * f00.x + w.y * f01.x + w.z * f10.x + w.w * f11.x;
                float r1 = w.x * f00.y + w.y * f01.y + w.z * f10.y + w.w * f11.y;
                __half2 hv = __floats2half2_rn(r0, r1);
                *(uint32_t*)(dstB + sw128((uint32_t)(p * 128 + lane * 4))) =
                    *(uint32_t*)&hv;
            }
            BAR_ARRIVE(1 + s, 512);
        }
    } else {
        // =================== CONSUMERS ===================
        int warpM = warp >> 1;   // 0..3
        int warpN = warp & 1;    // 0..1
        int q  = lane >> 3;
        int rr = lane & 7;
        int bRow  = warpN * 32 + (q >> 1) * 8 + rr;
        int bKoff = (q & 1) * 16;

        float acc[2][4][4];
#pragma unroll
        for (int mi = 0; mi < 2; mi++)
#pragma unroll
            for (int ni = 0; ni < 4; ni++)
#pragma unroll
                for (int e = 0; e < 4; e++) acc[mi][ni][e] = 0.0f;

        for (int t = 0; t < 9; t++) {
            int s = t & 3;
            BAR_SYNC(1 + s, 512);
            uint32_t bB = smem_u32(ring + s * 8192);

#pragma unroll
            for (int ks = 0; ks < 4; ks++) {
                uint32_t a[2][4];
#pragma unroll
                for (int mi = 0; mi < 2; mi++) {
                    uint4 f = g_wfM[((t * 4 + ks) * 8 + warpM * 2 + mi) * 32 + lane];
                    a[mi][0] = f.x; a[mi][1] = f.y; a[mi][2] = f.z; a[mi][3] = f.w;
                }
                uint32_t bf[4][2];
#pragma unroll
                for (int j2 = 0; j2 < 2; j2++) {
                    uint32_t addr = bB +
                        sw128((uint32_t)((bRow + j2 * 16) * 128 + ks * 32 + bKoff));
                    uint32_t r0, r1, r2, r3;
                    LDMX4(r0, r1, r2, r3, addr);
                    bf[j2 * 2 + 0][0] = r0; bf[j2 * 2 + 0][1] = r1;
                    bf[j2 * 2 + 1][0] = r2; bf[j2 * 2 + 1][1] = r3;
                }
#pragma unroll
                for (int mi = 0; mi < 2; mi++)
#pragma unroll
                    for (int ni = 0; ni < 4; ni++)
                        HMMA(acc[mi][ni], a[mi], bf[ni]);
            }
            BAR_ARRIVE(5 + s, 512);
        }

        // ---- epilogue ----
#pragma unroll
        for (int mi = 0; mi < 2; mi++) {
            int oc0 = warpM * 32 + mi * 16 + (lane >> 2);
            float bv0 = bias[oc0];
            float bv1 = bias[oc0 + 8];
            float* row0 = out + (((size_t)b * OCH + oc0) * HO + h) * WO + w0;
            float* row1 = row0 + 8 * (HO * WO);
#pragma unroll
            for (int ni = 0; ni < 4; ni++) {
                int n = warpN * 32 + ni * 8 + (lane & 3) * 2;
                *(float2*)(row0 + n) =
                    make_float2(acc[mi][ni][0] + bv0, acc[mi][ni][1] + bv0);
                *(float2*)(row1 + n) =
                    make_float2(acc[mi][ni][2] + bv1, acc[mi][ni][3] + bv1);
            }
        }
    }
}

// ---------------------------------------------------------------------------
extern "C" void kernel_launch(void* const* d_in, const int* in_sizes, int n_in,
                              void* d_out, int out_size) {
    const float* x    = (const float*)d_in[0];
    const float* ow   = (const float*)d_in[1];
    const float* ob   = (const float*)d_in[2];
    const float* wt   = (const float*)d_in[3];
    const float* bias = (const float*)d_in[4];
    float* out = (float*)d_out;

    int offSmem  = 32768 + 1024;
    int mainSmem = 32768 + 9216 + 4608 + 1024;   // 47616
    cudaFuncSetAttribute(offset_mma_kernel,
                         cudaFuncAttributeMaxDynamicSharedMemorySize, offSmem);
    cudaFuncSetAttribute(deform_mma_kernel,
                         cudaFuncAttributeMaxDynamicSharedMemorySize, mainSmem);

    dim3 tb(32, 8);
    dim3 tg((H * W) / 32, 1, B);
    transpose_kernel<<<tg, tb>>>(x);

    wfragM_kernel<<<(9 * 4 * 8 * 32 + 255) / 256, 256>>>(wt);
    wfragO_kernel<<<(9 * 4 * 2 * 32 + 255) / 256, 256>>>(ow);

    offset_mma_kernel<<<B * HO, 256, offSmem>>>(ob);

    deform_mma_kernel<<<B * HO * 2, 512, mainSmem>>>(bias, out);
}

// round 14
// speedup vs baseline: 1.3406x; 1.3031x over previous
#include <cuda_runtime.h>
#include <cuda_fp16.h>
#include <math.h>
#include <stdint.h>

#define B 8
#define C 64
#define H 256
#define W 256
#define OCH 128
#define K2 9
#define HO 128
#define WO 128
#define CK 576

// ---------------- device scratch (allocation-free) ----------------
__device__ __align__(16) float g_xt[B * H * W * C];    // x NHWC fp32
__device__ __align__(16) __half g_xh[B * H * W * C];   // x NHWC fp16 (main gather)
__device__ __align__(16) uint4 g_wfM[9 * 4 * 8 * 32];  // main A frags [t][ks][f][lane]
__device__ __align__(16) uint4 g_wfOh[9 * 4 * 2 * 32]; // offset A frags hi
__device__ __align__(16) uint4 g_wfOl[9 * 4 * 2 * 32]; // offset A frags lo
__device__ __align__(16) float4 g_gw[B * HO * WO * 9]; // bilinear weights (mask folded)
__device__ __align__(16) uint2  g_gd[B * HO * WO * 9]; // base elem idx, (dx | dy<<16)

__device__ __forceinline__ uint32_t smem_u32(const void* p) {
    uint32_t a;
    asm("{ .reg .u64 t; cvta.to.shared.u64 t, %1; cvt.u32.u64 %0, t; }"
        : "=r"(a) : "l"(p));
    return a;
}
__device__ __forceinline__ uint32_t sw128(uint32_t off) {
    return off ^ ((off >> 3) & 0x70);
}
__device__ __forceinline__ uint32_t pack_h2(float a, float b) {
    __half2 t = __floats2half2_rn(a, b);
    return *(uint32_t*)&t;
}
#define LDMX4(r0, r1, r2, r3, addr)                                          \
    asm volatile("ldmatrix.sync.aligned.m8n8.x4.shared.b16 {%0,%1,%2,%3}, [%4];" \
                 : "=r"(r0), "=r"(r1), "=r"(r2), "=r"(r3) : "r"(addr))
#define HMMA(acc, a, b)                                                       \
    asm volatile(                                                             \
        "mma.sync.aligned.m16n8k16.row.col.f32.f16.f16.f32 "                  \
        "{%0,%1,%2,%3}, {%4,%5,%6,%7}, {%8,%9}, {%0,%1,%2,%3};"               \
        : "+f"(acc[0]), "+f"(acc[1]), "+f"(acc[2]), "+f"(acc[3])              \
        : "r"(a[0]), "r"(a[1]), "r"(a[2]), "r"(a[3]), "r"(b[0]), "r"(b[1]))

// ---------------------------------------------------------------------------
// Kernel 0: NCHW fp32 -> NHWC fp32 + fp16
// ---------------------------------------------------------------------------
__global__ void transpose_kernel(const float* __restrict__ x) {
    __shared__ float tile[64][33];
    int b  = blockIdx.z;
    int s0 = blockIdx.x * 32;
    int tx = threadIdx.x, ty = threadIdx.y;
    const float* xb = x + (size_t)b * (C * H * W);
#pragma unroll
    for (int cy = ty; cy < 64; cy += 8)
        tile[cy][tx] = xb[(size_t)cy * (H * W) + s0 + tx];
    __syncthreads();
    size_t obase = (size_t)b * (H * W * C);
#pragma unroll
    for (int pp = 0; pp < 4; pp++) {
        int p = ty + pp * 8;
        float2 v = make_float2(tile[2 * tx][p], tile[2 * tx + 1][p]);
        size_t o = obase + (size_t)(s0 + p) * C + 2 * tx;
        *(float2*)(g_xt + o) = v;
        __half2 hv = __floats2half2_rn(v.x, v.y);
        *(uint32_t*)(g_xh + o) = *(uint32_t*)&hv;
    }
}

// ---------------------------------------------------------------------------
// Kernel 0b: main weights -> A fragments
// ---------------------------------------------------------------------------
__global__ void wfragM_kernel(const float* __restrict__ wt) {
    int j = blockIdx.x * 256 + threadIdx.x;
    if (j >= 9 * 4 * 8 * 32) return;
    int lane = j & 31;
    int f    = (j >> 5) & 7;
    int ks   = (j >> 8) & 3;
    int t    = j >> 10;
    int r  = lane >> 2;
    int c2 = lane & 3;
    int oc0 = f * 16 + r;
    int ch0 = ks * 16 + c2 * 2;
#define WV(oc, ch) wt[(oc) * CK + (ch) * 9 + t]
    uint4 o;
    o.x = pack_h2(WV(oc0, ch0),         WV(oc0, ch0 + 1));
    o.y = pack_h2(WV(oc0 + 8, ch0),     WV(oc0 + 8, ch0 + 1));
    o.z = pack_h2(WV(oc0, ch0 + 8),     WV(oc0, ch0 + 9));
    o.w = pack_h2(WV(oc0 + 8, ch0 + 8), WV(oc0 + 8, ch0 + 9));
#undef WV
    g_wfM[j] = o;
}

// ---------------------------------------------------------------------------
// Kernel 0c: offset weights -> A fragments hi/lo (M=32, rows>=27 zero)
// ---------------------------------------------------------------------------
__global__ void wfragO_kernel(const float* __restrict__ ow) {
    int j = blockIdx.x * 256 + threadIdx.x;
    if (j >= 9 * 4 * 2 * 32) return;
    int lane = j & 31;
    int mi   = (j >> 5) & 1;
    int ks   = (j >> 6) & 3;
    int t    = j >> 8;
    int r  = lane >> 2;
    int c2 = lane & 3;
    int oc0 = mi * 16 + r;
    int ch0 = ks * 16 + c2 * 2;

    float v[2][2][2];
#pragma unroll
    for (int rh = 0; rh < 2; rh++)
#pragma unroll
        for (int chh = 0; chh < 2; chh++)
#pragma unroll
            for (int e = 0; e < 2; e++) {
                int oc = oc0 + rh * 8;
                int ch = ch0 + chh * 8 + e;
                v[rh][chh][e] = (oc < 27) ? ow[(oc * 64 + ch) * 9 + t] : 0.0f;
            }
    uint4 oh, ol;
#define SPLIT(dsth, dstl, a, b)                                              \
    {                                                                         \
        __half2 hh = __floats2half2_rn(a, b);                                 \
        float2 hf = __half22float2(hh);                                       \
        dsth = *(uint32_t*)&hh;                                               \
        __half2 lls = __floats2half2_rn((a) - hf.x, (b) - hf.y);              \
        dstl = *(uint32_t*)&lls;                                              \
    }
    SPLIT(oh.x, ol.x, v[0][0][0], v[0][0][1]);
    SPLIT(oh.y, ol.y, v[1][0][0], v[1][0][1]);
    SPLIT(oh.z, ol.z, v[0][1][0], v[0][1][1]);
    SPLIT(oh.w, ol.w, v[1][1][0], v[1][1][1]);
#undef SPLIT
    g_wfOh[j] = oh;
    g_wfOl[j] = ol;
}

// ---------------------------------------------------------------------------
// Kernel 1: offset conv via split-fp16 mma + fused bilinear-param precompute.
// Block = (b,h): M=32(27) x N=128 x K=576. smem 32KB. Quad-channel gather.
// ---------------------------------------------------------------------------
__global__ void __launch_bounds__(256, 4)
offset_mma_kernel(const float* __restrict__ ob) {
    extern __shared__ char smraw[];
    char* smb = (char*)(((uintptr_t)smraw + 1023) & ~(uintptr_t)1023);
    char* Bh = smb;
    char* Bl = smb + 16384;

    int tid  = threadIdx.x;
    int warp = tid >> 5;
    int lane = tid & 31;

    int blk = blockIdx.x;   // b*128 + h
    int b   = blk >> 7;
    int h   = blk & 127;

    int q  = lane >> 3;
    int rr = lane & 7;
    int bRowB = warp * 16 + (q >> 1) * 8 + rr;
    int bKoff = (q & 1) * 16;

    float acc[2][2][4];
#pragma unroll
    for (int mi = 0; mi < 2; mi++)
#pragma unroll
        for (int ni = 0; ni < 2; ni++)
#pragma unroll
            for (int e = 0; e < 4; e++) acc[mi][ni][e] = 0.0f;

    size_t xbase = (size_t)b * (H * W * C);
    int pg = lane >> 4;     // position within pair
    int l4 = lane & 15;     // channel quad index
    uint32_t bhB = smem_u32(Bh);
    uint32_t blB = smem_u32(Bl);

    for (int t = 0; t < 9; t++) {
        // ---- gather tap t: 16 positions per warp, 2 per pass ----
        {
            int ky = t / 3;
            int kx = t - ky * 3;
            int iy = 2 * h - 1 + ky;
            bool yok = (iy >= 0) && (iy < H);
            const float* rowb = g_xt + xbase + (size_t)iy * (W * C) + 4 * l4;
#pragma unroll
            for (int pass = 0; pass < 8; pass++) {
                int p  = warp * 16 + pass * 2 + pg;
                int ix = 2 * p - 1 + kx;
                float4 v = make_float4(0.0f, 0.0f, 0.0f, 0.0f);
                if (yok && ix >= 0 && ix < W)
                    v = *(const float4*)(rowb + (size_t)ix * C);
                __half2 h0 = __floats2half2_rn(v.x, v.y);
                __half2 h1 = __floats2half2_rn(v.z, v.w);
                float2 f0 = __half22float2(h0);
                float2 f1 = __half22float2(h1);
                __half2 l0 = __floats2half2_rn(v.x - f0.x, v.y - f0.y);
                __half2 l1 = __floats2half2_rn(v.z - f1.x, v.w - f1.y);
                uint32_t so = sw128((uint32_t)(p * 128 + l4 * 8));
                *(uint2*)(Bh + so) = make_uint2(*(uint32_t*)&h0, *(uint32_t*)&h1);
                *(uint2*)(Bl + so) = make_uint2(*(uint32_t*)&l0, *(uint32_t*)&l1);
            }
        }
        __syncthreads();

#pragma unroll
        for (int ks = 0; ks < 4; ks++) {
            uint32_t ah[2][4], al[2][4], bh[2][2], bl[2][2];
#pragma unroll
            for (int mi = 0; mi < 2; mi++) {
                uint4 fh = g_wfOh[((t * 4 + ks) * 2 + mi) * 32 + lane];
                uint4 fl = g_wfOl[((t * 4 + ks) * 2 + mi) * 32 + lane];
                ah[mi][0] = fh.x; ah[mi][1] = fh.y; ah[mi][2] = fh.z; ah[mi][3] = fh.w;
                al[mi][0] = fl.x; al[mi][1] = fl.y; al[mi][2] = fl.z; al[mi][3] = fl.w;
            }
            {
                uint32_t boff = sw128((uint32_t)(bRowB * 128 + ks * 32 + bKoff));
                uint32_t r0, r1, r2, r3;
                LDMX4(r0, r1, r2, r3, bhB + boff);
                bh[0][0] = r0; bh[0][1] = r1; bh[1][0] = r2; bh[1][1] = r3;
                LDMX4(r0, r1, r2, r3, blB + boff);
                bl[0][0] = r0; bl[0][1] = r1; bl[1][0] = r2; bl[1][1] = r3;
            }
#pragma unroll
            for (int mi = 0; mi < 2; mi++)
#pragma unroll
                for (int ni = 0; ni < 2; ni++) {
                    HMMA(acc[mi][ni], ah[mi], bh[ni]);
                    HMMA(acc[mi][ni], ah[mi], bl[ni]);
                    HMMA(acc[mi][ni], al[mi], bh[ni]);
                }
        }
        __syncthreads();
    }

    // ---- epilogue: offsets -> smem (reuse Bh region, 16KB) ----
    float* smOff = (float*)Bh;  // [128][32]
    {
        int ocb  = lane >> 2;
        int posb = warp * 16 + (lane & 3) * 2;
#pragma unroll
        for (int mi = 0; mi < 2; mi++) {
#pragma unroll
            for (int eh = 0; eh < 2; eh++) {
                int oc = mi * 16 + eh * 8 + ocb;
                if (oc >= 27) continue;
                float bv = ob[oc];
                bool sig = (oc >= 18);
#pragma unroll
                for (int ni = 0; ni < 2; ni++) {
#pragma unroll
                    for (int e0 = 0; e0 < 2; e0++) {
                        float v = acc[mi][ni][eh * 2 + e0] + bv;
                        if (sig) v = 1.0f / (1.0f + __expf(-v));
                        int pos = posb + ni * 8 + e0;
                        smOff[pos * 32 + oc] = v;
                    }
                }
            }
        }
    }
    __syncthreads();

    // ---- param phase: 1152 (p,t) items ----
    float hyf = (float)(2 * h - 1);
    for (int j = tid; j < 128 * 9; j += 256) {
        int p = j / 9;
        int t = j - p * 9;
        float offx = smOff[p * 32 + t];
        float offy = smOff[p * 32 + 9 + t];
        float m    = smOff[p * 32 + 18 + t];

        float py = offy + (float)(t / 3) + hyf;
        float px = offx + (float)(t - (t / 3) * 3) + (float)(2 * p - 1);

        float y0f = floorf(py), x0f = floorf(px);
        float y1f = y0f + 1.0f, x1f = x0f + 1.0f;
        float wy1 = py - y0f, wy0 = 1.0f - wy1;
        float wx1 = px - x0f, wx0 = 1.0f - wx1;

        bool vy0 = (y0f >= 0.0f) && (y0f <= (float)(H - 1));
        bool vy1 = (y1f >= 0.0f) && (y1f <= (float)(H - 1));
        bool vx0 = (x0f >= 0.0f) && (x0f <= (float)(W - 1));
        bool vx1 = (x1f >= 0.0f) && (x1f <= (float)(W - 1));

        float w00 = (vy0 && vx0) ? wy0 * wx0 * m : 0.0f;
        float w01 = (vy0 && vx1) ? wy0 * wx1 * m : 0.0f;
        float w10 = (vy1 && vx0) ? wy1 * wx0 * m : 0.0f;
        float w11 = (vy1 && vx1) ? wy1 * wx1 * m : 0.0f;

        int yi0 = min(max((int)y0f, 0), H - 1);
        int yi1 = min(max((int)y1f, 0), H - 1);
        int xi0 = min(max((int)x0f, 0), W - 1);
        int xi1 = min(max((int)x1f, 0), W - 1);

        uint32_t base = (uint32_t)((yi0 * W + xi0) * C);
        uint32_t d = (uint32_t)((xi1 - xi0) * C) |
                     ((uint32_t)((yi1 - yi0) * W * C) << 16);

        int gi = (blk * 128 + p) * 9 + t;
        g_gw[gi] = make_float4(w00, w01, w10, w11);
        g_gd[gi] = make_uint2(base, d);
    }
}

// ---------------------------------------------------------------------------
// Kernel 2: deformable gather (fp16 x, quad channels) + mma.sync GEMM.
// Block = half-row: M=128 oc x N=64 pos, K=576. grid = B*HO*2 = 2048.
// 8 warps 4(M)x2(N); warp tile 32x32. smem: B db 16KB + params 13.5KB.
// ---------------------------------------------------------------------------
__global__ void __launch_bounds__(256, 3)
deform_mma_kernel(const float* __restrict__ bias, float* __restrict__ out) {
    extern __shared__ char smraw[];
    char* smb = (char*)(((uintptr_t)smraw + 1023) & ~(uintptr_t)1023);
    char* smB[2] = {smb, smb + 8192};
    float4* spW = (float4*)(smb + 16384);           // [64*9]
    uint2*  spD = (uint2*)(smb + 16384 + 9216);     // [64*9]

    int tid   = threadIdx.x;
    int warp  = tid >> 5;
    int lane  = tid & 31;
    int warpM = warp >> 1;   // 0..3
    int warpN = warp & 1;    // 0..1

    int blk  = blockIdx.x;   // ((b*128+h)*2 + half)
    int row  = blk >> 1;
    int b    = row >> 7;
    int h    = row & 127;
    int w0   = (blk & 1) * 64;

    int q  = lane >> 3;
    int rr = lane & 7;
    int bRow  = warpN * 32 + (q >> 1) * 8 + rr;
    int bKoff = (q & 1) * 16;

    float acc[2][4][4];
#pragma unroll
    for (int mi = 0; mi < 2; mi++)
#pragma unroll
        for (int ni = 0; ni < 4; ni++)
#pragma unroll
            for (int e = 0; e < 4; e++) acc[mi][ni][e] = 0.0f;

    const __half* xh = g_xh + (size_t)b * (H * W * C);
    int pg = lane >> 4;     // position within pair
    int l4 = lane & 15;     // channel quad
    int gbase = (row * 128 + w0) * 9;

    // ---- stage all 576 params for this block into smem ----
#pragma unroll
    for (int j = tid; j < 576; j += 256) {
        spW[j] = g_gw[gbase + j];
        spD[j] = g_gd[gbase + j];
    }
    __syncthreads();

    auto gatherTap = [&](int t, char* dstB) {
#pragma unroll
        for (int pass = 0; pass < 4; pass++) {
            int p  = warp * 8 + pass * 2 + pg;   // 0..63 within half-row
            float4 w = spW[p * 9 + t];
            uint2 dd = spD[p * 9 + t];
            const __half* base = xh + dd.x + 4 * l4;
            uint32_t dx = dd.y & 0xffffu;
            uint32_t dy = dd.y >> 16;
            uint2 q00 = *(const uint2*)(base);
            uint2 q01 = *(const uint2*)(base + dx);
            uint2 q10 = *(const uint2*)(base + dy);
            uint2 q11 = *(const uint2*)(base + dx + dy);

            float2 a00 = __half22float2(*(__half2*)&q00.x);
            float2 b00 = __half22float2(*(__half2*)&q00.y);
            float2 a01 = __half22float2(*(__half2*)&q01.x);
            float2 b01 = __half22float2(*(__half2*)&q01.y);
            float2 a10 = __half22float2(*(__half2*)&q10.x);
            float2 b10 = __half22float2(*(__half2*)&q10.y);
            float2 a11 = __half22float2(*(__half2*)&q11.x);
            float2 b11 = __half22float2(*(__half2*)&q11.y);

            float r0 = w.x * a00.x + w.y * a01.x + w.z * a10.x + w.w * a11.x;
            float r1 = w.x * a00.y + w.y * a01.y + w.z * a10.y + w.w * a11.y;
            float r2 = w.x * b00.x + w.y * b01.x + w.z * b10.x + w.w * b11.x;
            float r3 = w.x * b00.y + w.y * b01.y + w.z * b10.y + w.w * b11.y;

            __half2 hv0 = __floats2half2_rn(r0, r1);
            __half2 hv1 = __floats2half2_rn(r2, r3);
            *(uint2*)(dstB + sw128((uint32_t)(p * 128 + l4 * 8))) =
                make_uint2(*(uint32_t*)&hv0, *(uint32_t*)&hv1);
        }
    };

    gatherTap(0, smB[0]);
    __syncthreads();

    for (int t = 0; t < 9; t++) {
        int cur = t & 1;
        uint32_t bB = smem_u32(smB[cur]);

        // prefetch next tap's B while MMA runs on current
        if (t < 8) gatherTap(t + 1, smB[cur ^ 1]);

#pragma unroll
        for (int ks = 0; ks < 4; ks++) {
            uint32_t a[2][4];
#pragma unroll
            for (int mi = 0; mi < 2; mi++) {
                uint4 f = g_wfM[((t * 4 + ks) * 8 + warpM * 2 + mi) * 32 + lane];
                a[mi][0] = f.x; a[mi][1] = f.y; a[mi][2] = f.z; a[mi][3] = f.w;
            }
            uint32_t bf[4][2];
#pragma unroll
            for (int j2 = 0; j2 < 2; j2++) {
                uint32_t addr = bB +
                    sw128((uint32_t)((bRow + j2 * 16) * 128 + ks * 32 + bKoff));
                uint32_t r0, r1, r2, r3;
                LDMX4(r0, r1, r2, r3, addr);
                bf[j2 * 2 + 0][0] = r0; bf[j2 * 2 + 0][1] = r1;
                bf[j2 * 2 + 1][0] = r2; bf[j2 * 2 + 1][1] = r3;
            }
#pragma unroll
            for (int mi = 0; mi < 2; mi++)
#pragma unroll
                for (int ni = 0; ni < 4; ni++)
                    HMMA(acc[mi][ni], a[mi], bf[ni]);
        }
        __syncthreads();
    }

    // ---- epilogue ----
#pragma unroll
    for (int mi = 0; mi < 2; mi++) {
        int oc0 = warpM * 32 + mi * 16 + (lane >> 2);
        float bv0 = bias[oc0];
        float bv1 = bias[oc0 + 8];
        float* row0 = out + (((size_t)b * OCH + oc0) * HO + h) * WO + w0;
        float* row1 = row0 + 8 * (HO * WO);
#pragma unroll
        for (int ni = 0; ni < 4; ni++) {
            int n = warpN * 32 + ni * 8 + (lane & 3) * 2;
            *(float2*)(row0 + n) =
                make_float2(acc[mi][ni][0] + bv0, acc[mi][ni][1] + bv0);
            *(float2*)(row1 + n) =
                make_float2(acc[mi][ni][2] + bv1, acc[mi][ni][3] + bv1);
        }
    }
}

// ---------------------------------------------------------------------------
extern "C" void kernel_launch(void* const* d_in, const int* in_sizes, int n_in,
                              void* d_out, int out_size) {
    const float* x    = (const float*)d_in[0];
    const float* ow   = (const float*)d_in[1];
    const float* ob   = (const float*)d_in[2];
    const float* wt   = (const float*)d_in[3];
    const float* bias = (const float*)d_in[4];
    float* out = (float*)d_out;

    int offSmem  = 32768 + 1024;
    int mainSmem = 16384 + 13824 + 1024;
    cudaFuncSetAttribute(offset_mma_kernel,
                         cudaFuncAttributeMaxDynamicSharedMemorySize, offSmem);
    cudaFuncSetAttribute(deform_mma_kernel,
                         cudaFuncAttributeMaxDynamicSharedMemorySize, mainSmem);

    dim3 tb(32, 8);
    dim3 tg((H * W) / 32, 1, B);
    transpose_kernel<<<tg, tb>>>(x);

    wfragM_kernel<<<(9 * 4 * 8 * 32 + 255) / 256, 256>>>(wt);
    wfragO_kernel<<<(9 * 4 * 2 * 32 + 255) / 256, 256>>>(ow);

    offset_mma_kernel<<<B * HO, 256, offSmem>>>(ob);

    deform_mma_kernel<<<B * HO * 2, 256, mainSmem>>>(bias, out);
}

// round 15
// speedup vs baseline: 1.4183x; 1.0579x over previous
#include <cuda_runtime.h>
#include <cuda_fp16.h>
#include <math.h>
#include <stdint.h>

#define B 8
#define C 64
#define H 256
#define W 256
#define OCH 128
#define K2 9
#define HO 128
#define WO 128
#define CK 576

// ---------------- device scratch (allocation-free) ----------------
__device__ __align__(16) float g_xt[B * H * W * C];    // x NHWC fp32
__device__ __align__(16) __half g_xh[B * H * W * C];   // x NHWC fp16 (main gather)
__device__ __align__(16) uint4 g_wfM[9 * 4 * 8 * 32];  // main A frags [t][ks][f][lane]
__device__ __align__(16) uint4 g_wfOh[9 * 4 * 2 * 32]; // offset A frags hi
__device__ __align__(16) uint4 g_wfOl[9 * 4 * 2 * 32]; // offset A frags lo
__device__ __align__(16) float4 g_gw[B * HO * WO * 9]; // bilinear weights (mask folded)
__device__ __align__(16) uint2  g_gd[B * HO * WO * 9]; // base elem idx, (dx | dy<<16)

__device__ __forceinline__ uint32_t smem_u32(const void* p) {
    uint32_t a;
    asm("{ .reg .u64 t; cvta.to.shared.u64 t, %1; cvt.u32.u64 %0, t; }"
        : "=r"(a) : "l"(p));
    return a;
}
__device__ __forceinline__ uint32_t sw128(uint32_t off) {
    return off ^ ((off >> 3) & 0x70);
}
__device__ __forceinline__ uint32_t pack_h2(float a, float b) {
    __half2 t = __floats2half2_rn(a, b);
    return *(uint32_t*)&t;
}
#define LDMX4(r0, r1, r2, r3, addr)                                          \
    asm volatile("ldmatrix.sync.aligned.m8n8.x4.shared.b16 {%0,%1,%2,%3}, [%4];" \
                 : "=r"(r0), "=r"(r1), "=r"(r2), "=r"(r3) : "r"(addr))
#define HMMA(acc, a, b)                                                       \
    asm volatile(                                                             \
        "mma.sync.aligned.m16n8k16.row.col.f32.f16.f16.f32 "                  \
        "{%0,%1,%2,%3}, {%4,%5,%6,%7}, {%8,%9}, {%0,%1,%2,%3};"               \
        : "+f"(acc[0]), "+f"(acc[1]), "+f"(acc[2]), "+f"(acc[3])              \
        : "r"(a[0]), "r"(a[1]), "r"(a[2]), "r"(a[3]), "r"(b[0]), "r"(b[1]))

// ---------------------------------------------------------------------------
// Kernel 0: NCHW fp32 -> NHWC fp32 + fp16
// ---------------------------------------------------------------------------
__global__ void transpose_kernel(const float* __restrict__ x) {
    __shared__ float tile[64][33];
    int b  = blockIdx.z;
    int s0 = blockIdx.x * 32;
    int tx = threadIdx.x, ty = threadIdx.y;
    const float* xb = x + (size_t)b * (C * H * W);
#pragma unroll
    for (int cy = ty; cy < 64; cy += 8)
        tile[cy][tx] = xb[(size_t)cy * (H * W) + s0 + tx];
    __syncthreads();
    size_t obase = (size_t)b * (H * W * C);
#pragma unroll
    for (int pp = 0; pp < 4; pp++) {
        int p = ty + pp * 8;
        float2 v = make_float2(tile[2 * tx][p], tile[2 * tx + 1][p]);
        size_t o = obase + (size_t)(s0 + p) * C + 2 * tx;
        *(float2*)(g_xt + o) = v;
        __half2 hv = __floats2half2_rn(v.x, v.y);
        *(uint32_t*)(g_xh + o) = *(uint32_t*)&hv;
    }
}

// ---------------------------------------------------------------------------
// Kernel 0b: main weights -> A fragments
// ---------------------------------------------------------------------------
__global__ void wfragM_kernel(const float* __restrict__ wt) {
    int j = blockIdx.x * 256 + threadIdx.x;
    if (j >= 9 * 4 * 8 * 32) return;
    int lane = j & 31;
    int f    = (j >> 5) & 7;
    int ks   = (j >> 8) & 3;
    int t    = j >> 10;
    int r  = lane >> 2;
    int c2 = lane & 3;
    int oc0 = f * 16 + r;
    int ch0 = ks * 16 + c2 * 2;
#define WV(oc, ch) wt[(oc) * CK + (ch) * 9 + t]
    uint4 o;
    o.x = pack_h2(WV(oc0, ch0),         WV(oc0, ch0 + 1));
    o.y = pack_h2(WV(oc0 + 8, ch0),     WV(oc0 + 8, ch0 + 1));
    o.z = pack_h2(WV(oc0, ch0 + 8),     WV(oc0, ch0 + 9));
    o.w = pack_h2(WV(oc0 + 8, ch0 + 8), WV(oc0 + 8, ch0 + 9));
#undef WV
    g_wfM[j] = o;
}

// ---------------------------------------------------------------------------
// Kernel 0c: offset weights -> A fragments hi/lo (M=32, rows>=27 zero)
// ---------------------------------------------------------------------------
__global__ void wfragO_kernel(const float* __restrict__ ow) {
    int j = blockIdx.x * 256 + threadIdx.x;
    if (j >= 9 * 4 * 2 * 32) return;
    int lane = j & 31;
    int mi   = (j >> 5) & 1;
    int ks   = (j >> 6) & 3;
    int t    = j >> 8;
    int r  = lane >> 2;
    int c2 = lane & 3;
    int oc0 = mi * 16 + r;
    int ch0 = ks * 16 + c2 * 2;

    float v[2][2][2];
#pragma unroll
    for (int rh = 0; rh < 2; rh++)
#pragma unroll
        for (int chh = 0; chh < 2; chh++)
#pragma unroll
            for (int e = 0; e < 2; e++) {
                int oc = oc0 + rh * 8;
                int ch = ch0 + chh * 8 + e;
                v[rh][chh][e] = (oc < 27) ? ow[(oc * 64 + ch) * 9 + t] : 0.0f;
            }
    uint4 oh, ol;
#define SPLIT(dsth, dstl, a, b)                                              \
    {                                                                         \
        __half2 hh = __floats2half2_rn(a, b);                                 \
        float2 hf = __half22float2(hh);                                       \
        dsth = *(uint32_t*)&hh;                                               \
        __half2 lls = __floats2half2_rn((a) - hf.x, (b) - hf.y);              \
        dstl = *(uint32_t*)&lls;                                              \
    }
    SPLIT(oh.x, ol.x, v[0][0][0], v[0][0][1]);
    SPLIT(oh.y, ol.y, v[1][0][0], v[1][0][1]);
    SPLIT(oh.z, ol.z, v[0][1][0], v[0][1][1]);
    SPLIT(oh.w, ol.w, v[1][1][0], v[1][1][1]);
#undef SPLIT
    g_wfOh[j] = oh;
    g_wfOl[j] = ol;
}

// ---------------------------------------------------------------------------
// Kernel 1: offset conv via split-fp16 mma + fused bilinear-param precompute.
// Block = (b,h): M=32(27) x N=128 x K=576. smem 32KB. Quad-channel gather.
// ---------------------------------------------------------------------------
__global__ void __launch_bounds__(256, 4)
offset_mma_kernel(const float* __restrict__ ob) {
    extern __shared__ char smraw[];
    char* smb = (char*)(((uintptr_t)smraw + 1023) & ~(uintptr_t)1023);
    char* Bh = smb;
    char* Bl = smb + 16384;

    int tid  = threadIdx.x;
    int warp = tid >> 5;
    int lane = tid & 31;

    int blk = blockIdx.x;   // b*128 + h
    int b   = blk >> 7;
    int h   = blk & 127;

    int q  = lane >> 3;
    int rr = lane & 7;
    int bRowB = warp * 16 + (q >> 1) * 8 + rr;
    int bKoff = (q & 1) * 16;

    float acc[2][2][4];
#pragma unroll
    for (int mi = 0; mi < 2; mi++)
#pragma unroll
        for (int ni = 0; ni < 2; ni++)
#pragma unroll
            for (int e = 0; e < 4; e++) acc[mi][ni][e] = 0.0f;

    size_t xbase = (size_t)b * (H * W * C);
    int pg = lane >> 4;     // position within pair
    int l4 = lane & 15;     // channel quad index
    uint32_t bhB = smem_u32(Bh);
    uint32_t blB = smem_u32(Bl);

    for (int t = 0; t < 9; t++) {
        // ---- gather tap t: 16 positions per warp, 2 per pass ----
        {
            int ky = t / 3;
            int kx = t - ky * 3;
            int iy = 2 * h - 1 + ky;
            bool yok = (iy >= 0) && (iy < H);
            const float* rowb = g_xt + xbase + (size_t)iy * (W * C) + 4 * l4;
#pragma unroll
            for (int pass = 0; pass < 8; pass++) {
                int p  = warp * 16 + pass * 2 + pg;
                int ix = 2 * p - 1 + kx;
                float4 v = make_float4(0.0f, 0.0f, 0.0f, 0.0f);
                if (yok && ix >= 0 && ix < W)
                    v = *(const float4*)(rowb + (size_t)ix * C);
                __half2 h0 = __floats2half2_rn(v.x, v.y);
                __half2 h1 = __floats2half2_rn(v.z, v.w);
                float2 f0 = __half22float2(h0);
                float2 f1 = __half22float2(h1);
                __half2 l0 = __floats2half2_rn(v.x - f0.x, v.y - f0.y);
                __half2 l1 = __floats2half2_rn(v.z - f1.x, v.w - f1.y);
                uint32_t so = sw128((uint32_t)(p * 128 + l4 * 8));
                *(uint2*)(Bh + so) = make_uint2(*(uint32_t*)&h0, *(uint32_t*)&h1);
                *(uint2*)(Bl + so) = make_uint2(*(uint32_t*)&l0, *(uint32_t*)&l1);
            }
        }
        __syncthreads();

#pragma unroll
        for (int ks = 0; ks < 4; ks++) {
            uint32_t ah[2][4], al[2][4], bh[2][2], bl[2][2];
#pragma unroll
            for (int mi = 0; mi < 2; mi++) {
                uint4 fh = g_wfOh[((t * 4 + ks) * 2 + mi) * 32 + lane];
                uint4 fl = g_wfOl[((t * 4 + ks) * 2 + mi) * 32 + lane];
                ah[mi][0] = fh.x; ah[mi][1] = fh.y; ah[mi][2] = fh.z; ah[mi][3] = fh.w;
                al[mi][0] = fl.x; al[mi][1] = fl.y; al[mi][2] = fl.z; al[mi][3] = fl.w;
            }
            {
                uint32_t boff = sw128((uint32_t)(bRowB * 128 + ks * 32 + bKoff));
                uint32_t r0, r1, r2, r3;
                LDMX4(r0, r1, r2, r3, bhB + boff);
                bh[0][0] = r0; bh[0][1] = r1; bh[1][0] = r2; bh[1][1] = r3;
                LDMX4(r0, r1, r2, r3, blB + boff);
                bl[0][0] = r0; bl[0][1] = r1; bl[1][0] = r2; bl[1][1] = r3;
            }
#pragma unroll
            for (int mi = 0; mi < 2; mi++)
#pragma unroll
                for (int ni = 0; ni < 2; ni++) {
                    HMMA(acc[mi][ni], ah[mi], bh[ni]);
                    HMMA(acc[mi][ni], ah[mi], bl[ni]);
                    HMMA(acc[mi][ni], al[mi], bh[ni]);
                }
        }
        __syncthreads();
    }

    // ---- epilogue: offsets -> smem (reuse Bh region, 16KB) ----
    float* smOff = (float*)Bh;  // [128][32]
    {
        int ocb  = lane >> 2;
        int posb = warp * 16 + (lane & 3) * 2;
#pragma unroll
        for (int mi = 0; mi < 2; mi++) {
#pragma unroll
            for (int eh = 0; eh < 2; eh++) {
                int oc = mi * 16 + eh * 8 + ocb;
                if (oc >= 27) continue;
                float bv = ob[oc];
                bool sig = (oc >= 18);
#pragma unroll
                for (int ni = 0; ni < 2; ni++) {
#pragma unroll
                    for (int e0 = 0; e0 < 2; e0++) {
                        float v = acc[mi][ni][eh * 2 + e0] + bv;
                        if (sig) v = 1.0f / (1.0f + __expf(-v));
                        int pos = posb + ni * 8 + e0;
                        smOff[pos * 32 + oc] = v;
                    }
                }
            }
        }
    }
    __syncthreads();

    // ---- param phase: 1152 (p,t) items ----
    float hyf = (float)(2 * h - 1);
    for (int j = tid; j < 128 * 9; j += 256) {
        int p = j / 9;
        int t = j - p * 9;
        float offx = smOff[p * 32 + t];
        float offy = smOff[p * 32 + 9 + t];
        float m    = smOff[p * 32 + 18 + t];

        float py = offy + (float)(t / 3) + hyf;
        float px = offx + (float)(t - (t / 3) * 3) + (float)(2 * p - 1);

        float y0f = floorf(py), x0f = floorf(px);
        float y1f = y0f + 1.0f, x1f = x0f + 1.0f;
        float wy1 = py - y0f, wy0 = 1.0f - wy1;
        float wx1 = px - x0f, wx0 = 1.0f - wx1;

        bool vy0 = (y0f >= 0.0f) && (y0f <= (float)(H - 1));
        bool vy1 = (y1f >= 0.0f) && (y1f <= (float)(H - 1));
        bool vx0 = (x0f >= 0.0f) && (x0f <= (float)(W - 1));
        bool vx1 = (x1f >= 0.0f) && (x1f <= (float)(W - 1));

        float w00 = (vy0 && vx0) ? wy0 * wx0 * m : 0.0f;
        float w01 = (vy0 && vx1) ? wy0 * wx1 * m : 0.0f;
        float w10 = (vy1 && vx0) ? wy1 * wx0 * m : 0.0f;
        float w11 = (vy1 && vx1) ? wy1 * wx1 * m : 0.0f;

        int yi0 = min(max((int)y0f, 0), H - 1);
        int yi1 = min(max((int)y1f, 0), H - 1);
        int xi0 = min(max((int)x0f, 0), W - 1);
        int xi1 = min(max((int)x1f, 0), W - 1);

        uint32_t base = (uint32_t)((yi0 * W + xi0) * C);
        uint32_t d = (uint32_t)((xi1 - xi0) * C) |
                     ((uint32_t)((yi1 - yi0) * W * C) << 16);

        int gi = (blk * 128 + p) * 9 + t;
        g_gw[gi] = make_float4(w00, w01, w10, w11);
        g_gd[gi] = make_uint2(base, d);
    }
}

// ---------------------------------------------------------------------------
// Kernel 2: deformable gather (fp16 x, OCTET channels: 8 lanes per position,
// LDG.128 corners) + mma.sync GEMM.
// Block = half-row: M=128 oc x N=64 pos, K=576. grid = B*HO*2 = 2048.
// 8 warps 4(M)x2(N); warp tile 32x32. smem: B db 16KB + params 13.5KB.
// ---------------------------------------------------------------------------
__global__ void __launch_bounds__(256, 3)
deform_mma_kernel(const float* __restrict__ bias, float* __restrict__ out) {
    extern __shared__ char smraw[];
    char* smb = (char*)(((uintptr_t)smraw + 1023) & ~(uintptr_t)1023);
    char* smB[2] = {smb, smb + 8192};
    float4* spW = (float4*)(smb + 16384);           // [64*9]
    uint2*  spD = (uint2*)(smb + 16384 + 9216);     // [64*9]

    int tid   = threadIdx.x;
    int warp  = tid >> 5;
    int lane  = tid & 31;
    int warpM = warp >> 1;   // 0..3
    int warpN = warp & 1;    // 0..1

    int blk  = blockIdx.x;   // ((b*128+h)*2 + half)
    int row  = blk >> 1;
    int b    = row >> 7;
    int h    = row & 127;
    int w0   = (blk & 1) * 64;

    int q  = lane >> 3;
    int rr = lane & 7;
    int bRow  = warpN * 32 + (q >> 1) * 8 + rr;
    int bKoff = (q & 1) * 16;

    float acc[2][4][4];
#pragma unroll
    for (int mi = 0; mi < 2; mi++)
#pragma unroll
        for (int ni = 0; ni < 4; ni++)
#pragma unroll
            for (int e = 0; e < 4; e++) acc[mi][ni][e] = 0.0f;

    const __half* xh = g_xh + (size_t)b * (H * W * C);
    int pg = lane >> 3;     // position within quad of positions (0..3)
    int l8 = lane & 7;      // channel octet index (8 ch each)
    int gbase = (row * 128 + w0) * 9;

    // ---- stage all 576 params for this block into smem ----
#pragma unroll
    for (int j = tid; j < 576; j += 256) {
        spW[j] = g_gw[gbase + j];
        spD[j] = g_gd[gbase + j];
    }
    __syncthreads();

    auto gatherTap = [&](int t, char* dstB) {
#pragma unroll
        for (int pass = 0; pass < 2; pass++) {
            int p  = warp * 8 + pass * 4 + pg;   // 0..63 within half-row
            float4 w = spW[p * 9 + t];
            uint2 dd = spD[p * 9 + t];
            const __half* base = xh + dd.x + 8 * l8;
            uint32_t dx = dd.y & 0xffffu;
            uint32_t dy = dd.y >> 16;
            uint4 q00 = *(const uint4*)(base);
            uint4 q01 = *(const uint4*)(base + dx);
            uint4 q10 = *(const uint4*)(base + dy);
            uint4 q11 = *(const uint4*)(base + dx + dy);

            uint32_t o[4];
#pragma unroll
            for (int c4 = 0; c4 < 4; c4++) {
                float2 a00 = __half22float2(*((__half2*)&q00 + c4));
                float2 a01 = __half22float2(*((__half2*)&q01 + c4));
                float2 a10 = __half22float2(*((__half2*)&q10 + c4));
                float2 a11 = __half22float2(*((__half2*)&q11 + c4));
                float r0 = w.x * a00.x + w.y * a01.x + w.z * a10.x + w.w * a11.x;
                float r1 = w.x * a00.y + w.y * a01.y + w.z * a10.y + w.w * a11.y;
                o[c4] = pack_h2(r0, r1);
            }
            *(uint4*)(dstB + sw128((uint32_t)(p * 128 + l8 * 16))) =
                make_uint4(o[0], o[1], o[2], o[3]);
        }
    };

    gatherTap(0, smB[0]);
    __syncthreads();

    for (int t = 0; t < 9; t++) {
        int cur = t & 1;
        uint32_t bB = smem_u32(smB[cur]);

        // prefetch next tap's B while MMA runs on current
        if (t < 8) gatherTap(t + 1, smB[cur ^ 1]);

#pragma unroll
        for (int ks = 0; ks < 4; ks++) {
            uint32_t a[2][4];
#pragma unroll
            for (int mi = 0; mi < 2; mi++) {
                uint4 f = g_wfM[((t * 4 + ks) * 8 + warpM * 2 + mi) * 32 + lane];
                a[mi][0] = f.x; a[mi][1] = f.y; a[mi][2] = f.z; a[mi][3] = f.w;
            }
            uint32_t bf[4][2];
#pragma unroll
            for (int j2 = 0; j2 < 2; j2++) {
                uint32_t addr = bB +
                    sw128((uint32_t)((bRow + j2 * 16) * 128 + ks * 32 + bKoff));
                uint32_t r0, r1, r2, r3;
                LDMX4(r0, r1, r2, r3, addr);
                bf[j2 * 2 + 0][0] = r0; bf[j2 * 2 + 0][1] = r1;
                bf[j2 * 2 + 1][0] = r2; bf[j2 * 2 + 1][1] = r3;
            }
#pragma unroll
            for (int mi = 0; mi < 2; mi++)
#pragma unroll
                for (int ni = 0; ni < 4; ni++)
                    HMMA(acc[mi][ni], a[mi], bf[ni]);
        }
        __syncthreads();
    }

    // ---- epilogue ----
#pragma unroll
    for (int mi = 0; mi < 2; mi++) {
        int oc0 = warpM * 32 + mi * 16 + (lane >> 2);
        float bv0 = bias[oc0];
        float bv1 = bias[oc0 + 8];
        float* row0 = out + (((size_t)b * OCH + oc0) * HO + h) * WO + w0;
        float* row1 = row0 + 8 * (HO * WO);
#pragma unroll
        for (int ni = 0; ni < 4; ni++) {
            int n = warpN * 32 + ni * 8 + (lane & 3) * 2;
            *(float2*)(row0 + n) =
                make_float2(acc[mi][ni][0] + bv0, acc[mi][ni][1] + bv0);
            *(float2*)(row1 + n) =
                make_float2(acc[mi][ni][2] + bv1, acc[mi][ni][3] + bv1);
        }
    }
}

// ---------------------------------------------------------------------------
extern "C" void kernel_launch(void* const* d_in, const int* in_sizes, int n_in,
                              void* d_out, int out_size) {
    const float* x    = (const float*)d_in[0];
    const float* ow   = (const float*)d_in[1];
    const float* ob   = (const float*)d_in[2];
    const float* wt   = (const float*)d_in[3];
    const float* bias = (const float*)d_in[4];
    float* out = (float*)d_out;

    int offSmem  = 32768 + 1024;
    int mainSmem = 16384 + 13824 + 1024;
    cudaFuncSetAttribute(offset_mma_kernel,
                         cudaFuncAttributeMaxDynamicSharedMemorySize, offSmem);
    cudaFuncSetAttribute(deform_mma_kernel,
                         cudaFuncAttributeMaxDynamicSharedMemorySize, mainSmem);

    dim3 tb(32, 8);
    dim3 tg((H * W) / 32, 1, B);
    transpose_kernel<<<tg, tb>>>(x);

    wfragM_kernel<<<(9 * 4 * 8 * 32 + 255) / 256, 256>>>(wt);
    wfragO_kernel<<<(9 * 4 * 2 * 32 + 255) / 256, 256>>>(ow);

    offset_mma_kernel<<<B * HO, 256, offSmem>>>(ob);

    deform_mma_kernel<<<B * HO * 2, 256, mainSmem>>>(bias, out);
}

// round 16
// speedup vs baseline: 1.5464x; 1.0903x over previous
#include <cuda_runtime.h>
#include <cuda_fp16.h>
#include <math.h>
#include <stdint.h>

#define B 8
#define C 64
#define H 256
#define W 256
#define OCH 128
#define K2 9
#define HO 128
#define WO 128
#define CK 576

// ---------------- device scratch (allocation-free) ----------------
__device__ __align__(16) __half g_xhh[B * H * W * C];  // x NHWC fp16 hi
__device__ __align__(16) __half g_xhl[B * H * W * C];  // x NHWC fp16 lo residual
__device__ __align__(16) uint4 g_wfM[9 * 4 * 8 * 32];  // main A frags [t][ks][f][lane]
__device__ __align__(16) uint4 g_wfOh[9 * 4 * 2 * 32]; // offset A frags hi
__device__ __align__(16) uint4 g_wfOl[9 * 4 * 2 * 32]; // offset A frags lo
__device__ __align__(16) float4 g_gw[B * HO * WO * 9]; // bilinear weights (mask folded)
__device__ __align__(16) uint2  g_gd[B * HO * WO * 9]; // base elem idx, (dx | dy<<16)

__device__ __forceinline__ uint32_t smem_u32(const void* p) {
    uint32_t a;
    asm("{ .reg .u64 t; cvta.to.shared.u64 t, %1; cvt.u32.u64 %0, t; }"
        : "=r"(a) : "l"(p));
    return a;
}
__device__ __forceinline__ uint32_t sw128(uint32_t off) {
    return off ^ ((off >> 3) & 0x70);
}
__device__ __forceinline__ uint32_t pack_h2(float a, float b) {
    __half2 t = __floats2half2_rn(a, b);
    return *(uint32_t*)&t;
}
#define LDMX4(r0, r1, r2, r3, addr)                                          \
    asm volatile("ldmatrix.sync.aligned.m8n8.x4.shared.b16 {%0,%1,%2,%3}, [%4];" \
                 : "=r"(r0), "=r"(r1), "=r"(r2), "=r"(r3) : "r"(addr))
#define HMMA(acc, a, b)                                                       \
    asm volatile(                                                             \
        "mma.sync.aligned.m16n8k16.row.col.f32.f16.f16.f32 "                  \
        "{%0,%1,%2,%3}, {%4,%5,%6,%7}, {%8,%9}, {%0,%1,%2,%3};"               \
        : "+f"(acc[0]), "+f"(acc[1]), "+f"(acc[2]), "+f"(acc[3])              \
        : "r"(a[0]), "r"(a[1]), "r"(a[2]), "r"(a[3]), "r"(b[0]), "r"(b[1]))

// ---------------------------------------------------------------------------
// Kernel 0: NCHW fp32 -> NHWC fp16 hi/lo split
// ---------------------------------------------------------------------------
__global__ void transpose_kernel(const float* __restrict__ x) {
    __shared__ float tile[64][33];
    int b  = blockIdx.z;
    int s0 = blockIdx.x * 32;
    int tx = threadIdx.x, ty = threadIdx.y;
    const float* xb = x + (size_t)b * (C * H * W);
#pragma unroll
    for (int cy = ty; cy < 64; cy += 8)
        tile[cy][tx] = xb[(size_t)cy * (H * W) + s0 + tx];
    __syncthreads();
    size_t obase = (size_t)b * (H * W * C);
#pragma unroll
    for (int pp = 0; pp < 4; pp++) {
        int p = ty + pp * 8;
        float v0 = tile[2 * tx][p];
        float v1 = tile[2 * tx + 1][p];
        __half2 hh = __floats2half2_rn(v0, v1);
        float2 hf = __half22float2(hh);
        __half2 ll = __floats2half2_rn(v0 - hf.x, v1 - hf.y);
        size_t o = obase + (size_t)(s0 + p) * C + 2 * tx;
        *(uint32_t*)(g_xhh + o) = *(uint32_t*)&hh;
        *(uint32_t*)(g_xhl + o) = *(uint32_t*)&ll;
    }
}

// ---------------------------------------------------------------------------
// Kernel 0b: main weights -> A fragments
// ---------------------------------------------------------------------------
__global__ void wfragM_kernel(const float* __restrict__ wt) {
    int j = blockIdx.x * 256 + threadIdx.x;
    if (j >= 9 * 4 * 8 * 32) return;
    int lane = j & 31;
    int f    = (j >> 5) & 7;
    int ks   = (j >> 8) & 3;
    int t    = j >> 10;
    int r  = lane >> 2;
    int c2 = lane & 3;
    int oc0 = f * 16 + r;
    int ch0 = ks * 16 + c2 * 2;
#define WV(oc, ch) wt[(oc) * CK + (ch) * 9 + t]
    uint4 o;
    o.x = pack_h2(WV(oc0, ch0),         WV(oc0, ch0 + 1));
    o.y = pack_h2(WV(oc0 + 8, ch0),     WV(oc0 + 8, ch0 + 1));
    o.z = pack_h2(WV(oc0, ch0 + 8),     WV(oc0, ch0 + 9));
    o.w = pack_h2(WV(oc0 + 8, ch0 + 8), WV(oc0 + 8, ch0 + 9));
#undef WV
    g_wfM[j] = o;
}

// ---------------------------------------------------------------------------
// Kernel 0c: offset weights -> A fragments hi/lo (M=32, rows>=27 zero)
// ---------------------------------------------------------------------------
__global__ void wfragO_kernel(const float* __restrict__ ow) {
    int j = blockIdx.x * 256 + threadIdx.x;
    if (j >= 9 * 4 * 2 * 32) return;
    int lane = j & 31;
    int mi   = (j >> 5) & 1;
    int ks   = (j >> 6) & 3;
    int t    = j >> 8;
    int r  = lane >> 2;
    int c2 = lane & 3;
    int oc0 = mi * 16 + r;
    int ch0 = ks * 16 + c2 * 2;

    float v[2][2][2];
#pragma unroll
    for (int rh = 0; rh < 2; rh++)
#pragma unroll
        for (int chh = 0; chh < 2; chh++)
#pragma unroll
            for (int e = 0; e < 2; e++) {
                int oc = oc0 + rh * 8;
                int ch = ch0 + chh * 8 + e;
                v[rh][chh][e] = (oc < 27) ? ow[(oc * 64 + ch) * 9 + t] : 0.0f;
            }
    uint4 oh, ol;
#define SPLIT(dsth, dstl, a, b)                                              \
    {                                                                         \
        __half2 hh = __floats2half2_rn(a, b);                                 \
        float2 hf = __half22float2(hh);                                       \
        dsth = *(uint32_t*)&hh;                                               \
        __half2 lls = __floats2half2_rn((a) - hf.x, (b) - hf.y);              \
        dstl = *(uint32_t*)&lls;                                              \
    }
    SPLIT(oh.x, ol.x, v[0][0][0], v[0][0][1]);
    SPLIT(oh.y, ol.y, v[1][0][0], v[1][0][1]);
    SPLIT(oh.z, ol.z, v[0][1][0], v[0][1][1]);
    SPLIT(oh.w, ol.w, v[1][1][0], v[1][1][1]);
#undef SPLIT
    g_wfOh[j] = oh;
    g_wfOl[j] = ol;
}

// ---------------------------------------------------------------------------
// Kernel 1: offset conv via split-fp16 mma + fused bilinear-param precompute.
// Block = (b,h): M=32(27) x N=128 x K=576. smem 32KB. Octet-channel gather
// (pre-split hi/lo fp16 x: bit-identical to in-kernel split of fp32 x).
// ---------------------------------------------------------------------------
__global__ void __launch_bounds__(256, 4)
offset_mma_kernel(const float* __restrict__ ob) {
    extern __shared__ char smraw[];
    char* smb = (char*)(((uintptr_t)smraw + 1023) & ~(uintptr_t)1023);
    char* Bh = smb;
    char* Bl = smb + 16384;

    int tid  = threadIdx.x;
    int warp = tid >> 5;
    int lane = tid & 31;

    int blk = blockIdx.x;   // b*128 + h
    int b   = blk >> 7;
    int h   = blk & 127;

    int q  = lane >> 3;
    int rr = lane & 7;
    int bRowB = warp * 16 + (q >> 1) * 8 + rr;
    int bKoff = (q & 1) * 16;

    float acc[2][2][4];
#pragma unroll
    for (int mi = 0; mi < 2; mi++)
#pragma unroll
        for (int ni = 0; ni < 2; ni++)
#pragma unroll
            for (int e = 0; e < 4; e++) acc[mi][ni][e] = 0.0f;

    size_t xbase = (size_t)b * (H * W * C);
    int pg = lane >> 3;     // 0..3 position within pass
    int l8 = lane & 7;      // channel octet (8 ch)
    uint32_t bhB = smem_u32(Bh);
    uint32_t blB = smem_u32(Bl);

    for (int t = 0; t < 9; t++) {
        // ---- gather tap t: 16 positions per warp, 4 per pass ----
        {
            int ky = t / 3;
            int kx = t - ky * 3;
            int iy = 2 * h - 1 + ky;
            bool yok = (iy >= 0) && (iy < H);
            size_t rowb = xbase + (size_t)iy * (W * C) + 8 * l8;
#pragma unroll
            for (int pass = 0; pass < 4; pass++) {
                int p  = warp * 16 + pass * 4 + pg;
                int ix = 2 * p - 1 + kx;
                uint4 vh = make_uint4(0, 0, 0, 0);
                uint4 vl = make_uint4(0, 0, 0, 0);
                if (yok && ix >= 0 && ix < W) {
                    size_t idx = rowb + (size_t)ix * C;
                    vh = *(const uint4*)(g_xhh + idx);
                    vl = *(const uint4*)(g_xhl + idx);
                }
                uint32_t so = sw128((uint32_t)(p * 128 + l8 * 16));
                *(uint4*)(Bh + so) = vh;
                *(uint4*)(Bl + so) = vl;
            }
        }
        __syncthreads();

#pragma unroll
        for (int ks = 0; ks < 4; ks++) {
            uint32_t ah[2][4], al[2][4], bh[2][2], bl[2][2];
#pragma unroll
            for (int mi = 0; mi < 2; mi++) {
                uint4 fh = g_wfOh[((t * 4 + ks) * 2 + mi) * 32 + lane];
                uint4 fl = g_wfOl[((t * 4 + ks) * 2 + mi) * 32 + lane];
                ah[mi][0] = fh.x; ah[mi][1] = fh.y; ah[mi][2] = fh.z; ah[mi][3] = fh.w;
                al[mi][0] = fl.x; al[mi][1] = fl.y; al[mi][2] = fl.z; al[mi][3] = fl.w;
            }
            {
                uint32_t boff = sw128((uint32_t)(bRowB * 128 + ks * 32 + bKoff));
                uint32_t r0, r1, r2, r3;
                LDMX4(r0, r1, r2, r3, bhB + boff);
                bh[0][0] = r0; bh[0][1] = r1; bh[1][0] = r2; bh[1][1] = r3;
                LDMX4(r0, r1, r2, r3, blB + boff);
                bl[0][0] = r0; bl[0][1] = r1; bl[1][0] = r2; bl[1][1] = r3;
            }
#pragma unroll
            for (int mi = 0; mi < 2; mi++)
#pragma unroll
                for (int ni = 0; ni < 2; ni++) {
                    HMMA(acc[mi][ni], ah[mi], bh[ni]);
                    HMMA(acc[mi][ni], ah[mi], bl[ni]);
                    HMMA(acc[mi][ni], al[mi], bh[ni]);
                }
        }
        __syncthreads();
    }

    // ---- epilogue: offsets -> smem (reuse Bh region, 16KB) ----
    float* smOff = (float*)Bh;  // [128][32]
    {
        int ocb  = lane >> 2;
        int posb = warp * 16 + (lane & 3) * 2;
#pragma unroll
        for (int mi = 0; mi < 2; mi++) {
#pragma unroll
            for (int eh = 0; eh < 2; eh++) {
                int oc = mi * 16 + eh * 8 + ocb;
                if (oc >= 27) continue;
                float bv = ob[oc];
                bool sig = (oc >= 18);
#pragma unroll
                for (int ni = 0; ni < 2; ni++) {
#pragma unroll
                    for (int e0 = 0; e0 < 2; e0++) {
                        float v = acc[mi][ni][eh * 2 + e0] + bv;
                        if (sig) v = 1.0f / (1.0f + __expf(-v));
                        int pos = posb + ni * 8 + e0;
                        smOff[pos * 32 + oc] = v;
                    }
                }
            }
        }
    }
    __syncthreads();

    // ---- param phase: 1152 (p,t) items ----
    float hyf = (float)(2 * h - 1);
    for (int j = tid; j < 128 * 9; j += 256) {
        int p = j / 9;
        int t = j - p * 9;
        float offx = smOff[p * 32 + t];
        float offy = smOff[p * 32 + 9 + t];
        float m    = smOff[p * 32 + 18 + t];

        float py = offy + (float)(t / 3) + hyf;
        float px = offx + (float)(t - (t / 3) * 3) + (float)(2 * p - 1);

        float y0f = floorf(py), x0f = floorf(px);
        float y1f = y0f + 1.0f, x1f = x0f + 1.0f;
        float wy1 = py - y0f, wy0 = 1.0f - wy1;
        float wx1 = px - x0f, wx0 = 1.0f - wx1;

        bool vy0 = (y0f >= 0.0f) && (y0f <= (float)(H - 1));
        bool vy1 = (y1f >= 0.0f) && (y1f <= (float)(H - 1));
        bool vx0 = (x0f >= 0.0f) && (x0f <= (float)(W - 1));
        bool vx1 = (x1f >= 0.0f) && (x1f <= (float)(W - 1));

        float w00 = (vy0 && vx0) ? wy0 * wx0 * m : 0.0f;
        float w01 = (vy0 && vx1) ? wy0 * wx1 * m : 0.0f;
        float w10 = (vy1 && vx0) ? wy1 * wx0 * m : 0.0f;
        float w11 = (vy1 && vx1) ? wy1 * wx1 * m : 0.0f;

        int yi0 = min(max((int)y0f, 0), H - 1);
        int yi1 = min(max((int)y1f, 0), H - 1);
        int xi0 = min(max((int)x0f, 0), W - 1);
        int xi1 = min(max((int)x1f, 0), W - 1);

        uint32_t base = (uint32_t)((yi0 * W + xi0) * C);
        uint32_t d = (uint32_t)((xi1 - xi0) * C) |
                     ((uint32_t)((yi1 - yi0) * W * C) << 16);

        int gi = (blk * 128 + p) * 9 + t;
        g_gw[gi] = make_float4(w00, w01, w10, w11);
        g_gd[gi] = make_uint2(base, d);
    }
}

// ---------------------------------------------------------------------------
// Kernel 2: deformable gather (fp16 x hi, octet channels, LDG.128 corners)
// + mma.sync GEMM. Block = half-row: M=128 x N=64, K=576. grid = 2048.
// 8 warps 4(M)x2(N); warp tile 32x32. smem: B db 16KB + params 13.5KB.
// ---------------------------------------------------------------------------
__global__ void __launch_bounds__(256, 3)
deform_mma_kernel(const float* __restrict__ bias, float* __restrict__ out) {
    extern __shared__ char smraw[];
    char* smb = (char*)(((uintptr_t)smraw + 1023) & ~(uintptr_t)1023);
    char* smB[2] = {smb, smb + 8192};
    float4* spW = (float4*)(smb + 16384);           // [64*9]
    uint2*  spD = (uint2*)(smb + 16384 + 9216);     // [64*9]

    int tid   = threadIdx.x;
    int warp  = tid >> 5;
    int lane  = tid & 31;
    int warpM = warp >> 1;   // 0..3
    int warpN = warp & 1;    // 0..1

    int blk  = blockIdx.x;   // ((b*128+h)*2 + half)
    int row  = blk >> 1;
    int b    = row >> 7;
    int h    = row & 127;
    int w0   = (blk & 1) * 64;

    int q  = lane >> 3;
    int rr = lane & 7;
    int bRow  = warpN * 32 + (q >> 1) * 8 + rr;
    int bKoff = (q & 1) * 16;

    float acc[2][4][4];
#pragma unroll
    for (int mi = 0; mi < 2; mi++)
#pragma unroll
        for (int ni = 0; ni < 4; ni++)
#pragma unroll
            for (int e = 0; e < 4; e++) acc[mi][ni][e] = 0.0f;

    const __half* xh = g_xhh + (size_t)b * (H * W * C);
    int pg = lane >> 3;     // position within quad (0..3)
    int l8 = lane & 7;      // channel octet
    int gbase = (row * 128 + w0) * 9;

    // ---- stage all 576 params for this block into smem ----
#pragma unroll
    for (int j = tid; j < 576; j += 256) {
        spW[j] = g_gw[gbase + j];
        spD[j] = g_gd[gbase + j];
    }
    __syncthreads();

    auto gatherTap = [&](int t, char* dstB) {
#pragma unroll
        for (int pass = 0; pass < 2; pass++) {
            int p  = warp * 8 + pass * 4 + pg;   // 0..63 within half-row
            float4 w = spW[p * 9 + t];
            uint2 dd = spD[p * 9 + t];
            const __half* base = xh + dd.x + 8 * l8;
            uint32_t dx = dd.y & 0xffffu;
            uint32_t dy = dd.y >> 16;
            uint4 q00 = *(const uint4*)(base);
            uint4 q01 = *(const uint4*)(base + dx);
            uint4 q10 = *(const uint4*)(base + dy);
            uint4 q11 = *(const uint4*)(base + dx + dy);

            uint32_t o[4];
#pragma unroll
            for (int c4 = 0; c4 < 4; c4++) {
                float2 a00 = __half22float2(*((__half2*)&q00 + c4));
                float2 a01 = __half22float2(*((__half2*)&q01 + c4));
                float2 a10 = __half22float2(*((__half2*)&q10 + c4));
                float2 a11 = __half22float2(*((__half2*)&q11 + c4));
                float r0 = w.x * a00.x + w.y * a01.x + w.z * a10.x + w.w * a11.x;
                float r1 = w.x * a00.y + w.y * a01.y + w.z * a10.y + w.w * a11.y;
                o[c4] = pack_h2(r0, r1);
            }
            *(uint4*)(dstB + sw128((uint32_t)(p * 128 + l8 * 16))) =
                make_uint4(o[0], o[1], o[2], o[3]);
        }
    };

    gatherTap(0, smB[0]);
    __syncthreads();

    for (int t = 0; t < 9; t++) {
        int cur = t & 1;
        uint32_t bB = smem_u32(smB[cur]);

        // prefetch next tap's B while MMA runs on current
        if (t < 8) gatherTap(t + 1, smB[cur ^ 1]);

#pragma unroll
        for (int ks = 0; ks < 4; ks++) {
            uint32_t a[2][4];
#pragma unroll
            for (int mi = 0; mi < 2; mi++) {
                uint4 f = g_wfM[((t * 4 + ks) * 8 + warpM * 2 + mi) * 32 + lane];
                a[mi][0] = f.x; a[mi][1] = f.y; a[mi][2] = f.z; a[mi][3] = f.w;
            }
            uint32_t bf[4][2];
#pragma unroll
            for (int j2 = 0; j2 < 2; j2++) {
                uint32_t addr = bB +
                    sw128((uint32_t)((bRow + j2 * 16) * 128 + ks * 32 + bKoff));
                uint32_t r0, r1, r2, r3;
                LDMX4(r0, r1, r2, r3, addr);
                bf[j2 * 2 + 0][0] = r0; bf[j2 * 2 + 0][1] = r1;
                bf[j2 * 2 + 1][0] = r2; bf[j2 * 2 + 1][1] = r3;
            }
#pragma unroll
            for (int mi = 0; mi < 2; mi++)
#pragma unroll
                for (int ni = 0; ni < 4; ni++)
                    HMMA(acc[mi][ni], a[mi], bf[ni]);
        }
        __syncthreads();
    }

    // ---- epilogue ----
#pragma unroll
    for (int mi = 0; mi < 2; mi++) {
        int oc0 = warpM * 32 + mi * 16 + (lane >> 2);
        float bv0 = bias[oc0];
        float bv1 = bias[oc0 + 8];
        float* row0 = out + (((size_t)b * OCH + oc0) * HO + h) * WO + w0;
        float* row1 = row0 + 8 * (HO * WO);
#pragma unroll
        for (int ni = 0; ni < 4; ni++) {
            int n = warpN * 32 + ni * 8 + (lane & 3) * 2;
            *(float2*)(row0 + n) =
                make_float2(acc[mi][ni][0] + bv0, acc[mi][ni][1] + bv0);
            *(float2*)(row1 + n) =
                make_float2(acc[mi][ni][2] + bv1, acc[mi][ni][3] + bv1);
        }
    }
}

// ---------------------------------------------------------------------------
extern "C" void kernel_launch(void* const* d_in, const int* in_sizes, int n_in,
                              void* d_out, int out_size) {
    const float* x    = (const float*)d_in[0];
    const float* ow   = (const float*)d_in[1];
    const float* ob   = (const float*)d_in[2];
    const float* wt   = (const float*)d_in[3];
    const float* bias = (const float*)d_in[4];
    float* out = (float*)d_out;

    int offSmem  = 32768 + 1024;
    int mainSmem = 16384 + 13824 + 1024;
    cudaFuncSetAttribute(offset_mma_kernel,
                         cudaFuncAttributeMaxDynamicSharedMemorySize, offSmem);
    cudaFuncSetAttribute(deform_mma_kernel,
                         cudaFuncAttributeMaxDynamicSharedMemorySize, mainSmem);

    dim3 tb(32, 8);
    dim3 tg((H * W) / 32, 1, B);
    transpose_kernel<<<tg, tb>>>(x);

    wfragM_kernel<<<(9 * 4 * 8 * 32 + 255) / 256, 256>>>(wt);
    wfragO_kernel<<<(9 * 4 * 2 * 32 + 255) / 256, 256>>>(ow);

    offset_mma_kernel<<<B * HO, 256, offSmem>>>(ob);

    deform_mma_kernel<<<B * HO * 2, 256, mainSmem>>>(bias, out);
}